// round 1
// baseline (speedup 1.0000x reference)
#include <cuda_runtime.h>
#include <cuda_bf16.h>

// ---------------------------------------------------------------------------
// AttentionBlock: b=4, n=2048, dim=2048, heads=16, d_head=128
// inputs: x, emb, W_emb, b_emb, g_norm, W_qkv, g_q, g_k, W_out (all fp32)
// out:    [4,2048,2048] fp32
// ---------------------------------------------------------------------------

#define B_     4
#define N_     2048
#define DIM_   2048
#define H_     16
#define DH_    128
#define TOK_   (B_ * N_)          // 8192
#define QKVC_  (3 * DIM_)         // 6144

// Scratch (static __device__ arrays: the sanctioned no-alloc workaround)
__device__ float g_ss[B_ * 2 * DIM_];                       // scale||shift  [4,4096]
__device__ float g_xn[(long long)TOK_ * DIM_];              // 64 MB
__device__ float g_qkv[(long long)TOK_ * QKVC_];            // 192 MB
__device__ float g_logits[(long long)B_ * H_ * N_ * N_];    // 1 GB
__device__ float g_otok[(long long)TOK_ * DIM_];            // 64 MB

// ---------------- packed f32x2 helpers --------------------------------------
__device__ __forceinline__ unsigned long long pack_dup(float x) {
    unsigned long long r;
    asm("mov.b64 %0, {%1, %1};" : "=l"(r) : "r"(__float_as_uint(x)));
    return r;
}
__device__ __forceinline__ void ffma2(unsigned long long& d,
                                      unsigned long long a,
                                      unsigned long long b) {
    asm("fma.rn.f32x2 %0, %1, %2, %0;" : "+l"(d) : "l"(a), "l"(b));
}
__device__ __forceinline__ float2 unpack2(unsigned long long v) {
    unsigned int lo, hi;
    asm("mov.b64 {%0, %1}, %2;" : "=r"(lo), "=r"(hi) : "l"(v));
    return make_float2(__uint_as_float(lo), __uint_as_float(hi));
}

// ---------------- block reductions (256-thread blocks) ----------------------
__device__ __forceinline__ float blk_sum256(float v) {
    __shared__ float red[8];
    __shared__ float tot;
    #pragma unroll
    for (int o = 16; o > 0; o >>= 1) v += __shfl_xor_sync(0xffffffffu, v, o);
    if ((threadIdx.x & 31) == 0) red[threadIdx.x >> 5] = v;
    __syncthreads();
    if (threadIdx.x == 0) {
        float s = 0.f;
        #pragma unroll
        for (int i = 0; i < 8; i++) s += red[i];
        tot = s;
    }
    __syncthreads();
    return tot;
}
__device__ __forceinline__ float blk_max256(float v) {
    __shared__ float red[8];
    __shared__ float tot;
    #pragma unroll
    for (int o = 16; o > 0; o >>= 1) v = fmaxf(v, __shfl_xor_sync(0xffffffffu, v, o));
    if ((threadIdx.x & 31) == 0) red[threadIdx.x >> 5] = v;
    __syncthreads();
    if (threadIdx.x == 0) {
        float s = red[0];
        #pragma unroll
        for (int i = 1; i < 8; i++) s = fmaxf(s, red[i]);
        tot = s;
    }
    __syncthreads();
    return tot;
}

// ---------------- K1: scale_shift = emb @ W_emb + b_emb ---------------------
__global__ void k_scale_shift(const float* __restrict__ emb,
                              const float* __restrict__ W,
                              const float* __restrict__ bias,
                              float* __restrict__ ss) {
    int c = blockIdx.x * 256 + threadIdx.x;     // 0..4095
    int b = blockIdx.y;
    const float* e = emb + b * DIM_;
    float acc = bias[c];
    const float* wp = W + c;
    #pragma unroll 8
    for (int k = 0; k < DIM_; k++)
        acc = fmaf(e[k], wp[(long long)k * (2 * DIM_)], acc);
    ss[b * (2 * DIM_) + c] = acc;
}

// ---------------- K2: xn = RMSNorm(x)*g*(1+scale)+shift ---------------------
__global__ void k_xnorm(const float* __restrict__ x,
                        const float* __restrict__ g,
                        const float* __restrict__ ss,
                        float* __restrict__ xn) {
    long long row = blockIdx.x;                 // 0..8191
    int b = (int)(row >> 11);
    const float4* xr = (const float4*)(x + row * DIM_);
    float4 v0 = xr[threadIdx.x];
    float4 v1 = xr[threadIdx.x + 256];
    float s = v0.x * v0.x + v0.y * v0.y + v0.z * v0.z + v0.w * v0.w
            + v1.x * v1.x + v1.y * v1.y + v1.z * v1.z + v1.w * v1.w;
    s = blk_sum256(s);
    float r = rsqrtf(s * (1.f / DIM_) + 1e-6f);
    const float* sc = ss + b * (2 * DIM_);
    const float* sh = sc + DIM_;
    float4* out = (float4*)(xn + row * DIM_);
    int c0 = threadIdx.x * 4;
    float4 o0, o1;
    o0.x = fmaf(v0.x * r * g[c0 + 0], 1.f + sc[c0 + 0], sh[c0 + 0]);
    o0.y = fmaf(v0.y * r * g[c0 + 1], 1.f + sc[c0 + 1], sh[c0 + 1]);
    o0.z = fmaf(v0.z * r * g[c0 + 2], 1.f + sc[c0 + 2], sh[c0 + 2]);
    o0.w = fmaf(v0.w * r * g[c0 + 3], 1.f + sc[c0 + 3], sh[c0 + 3]);
    int c1 = (threadIdx.x + 256) * 4;
    o1.x = fmaf(v1.x * r * g[c1 + 0], 1.f + sc[c1 + 0], sh[c1 + 0]);
    o1.y = fmaf(v1.y * r * g[c1 + 1], 1.f + sc[c1 + 1], sh[c1 + 1]);
    o1.z = fmaf(v1.z * r * g[c1 + 2], 1.f + sc[c1 + 2], sh[c1 + 2]);
    o1.w = fmaf(v1.w * r * g[c1 + 3], 1.f + sc[c1 + 3], sh[c1 + 3]);
    out[threadIdx.x] = o0;
    out[threadIdx.x + 256] = o1;
}

// ---------------- K4: per-head RMSNorm of q and k (in place) ----------------
__global__ void k_qknorm(float* __restrict__ qkv,
                         const float* __restrict__ gq,
                         const float* __restrict__ gk) {
    int row = blockIdx.x;                        // token 0..8191
    int h = threadIdx.x >> 5;                    // head 0..15
    int lane = threadIdx.x & 31;
    float* q = qkv + (long long)row * QKVC_ + h * DH_;
    float* k = q + DIM_;
    // q
    {
        float4 v = *(float4*)(q + lane * 4);
        float s = v.x * v.x + v.y * v.y + v.z * v.z + v.w * v.w;
        #pragma unroll
        for (int o = 16; o > 0; o >>= 1) s += __shfl_xor_sync(0xffffffffu, s, o);
        float r = rsqrtf(s * (1.f / DH_) + 1e-6f);
        v.x *= r * gq[lane * 4 + 0];
        v.y *= r * gq[lane * 4 + 1];
        v.z *= r * gq[lane * 4 + 2];
        v.w *= r * gq[lane * 4 + 3];
        *(float4*)(q + lane * 4) = v;
    }
    // k
    {
        float4 v = *(float4*)(k + lane * 4);
        float s = v.x * v.x + v.y * v.y + v.z * v.z + v.w * v.w;
        #pragma unroll
        for (int o = 16; o > 0; o >>= 1) s += __shfl_xor_sync(0xffffffffu, s, o);
        float r = rsqrtf(s * (1.f / DH_) + 1e-6f);
        v.x *= r * gk[lane * 4 + 0];
        v.y *= r * gk[lane * 4 + 1];
        v.z *= r * gk[lane * 4 + 2];
        v.w *= r * gk[lane * 4 + 3];
        *(float4*)(k + lane * 4) = v;
    }
}

// ---------------- K6: row softmax over 2048 ---------------------------------
__global__ void k_softmax(float* __restrict__ logits) {
    long long row = blockIdx.x;                  // 0..131071
    float4* p = (float4*)(logits + row * (long long)N_);
    float4 v0 = p[threadIdx.x];
    float4 v1 = p[threadIdx.x + 256];
    float mx = fmaxf(fmaxf(fmaxf(v0.x, v0.y), fmaxf(v0.z, v0.w)),
                     fmaxf(fmaxf(v1.x, v1.y), fmaxf(v1.z, v1.w)));
    mx = blk_max256(mx);
    v0.x = __expf(v0.x - mx); v0.y = __expf(v0.y - mx);
    v0.z = __expf(v0.z - mx); v0.w = __expf(v0.w - mx);
    v1.x = __expf(v1.x - mx); v1.y = __expf(v1.y - mx);
    v1.z = __expf(v1.z - mx); v1.w = __expf(v1.w - mx);
    float s = v0.x + v0.y + v0.z + v0.w + v1.x + v1.y + v1.z + v1.w;
    s = blk_sum256(s);
    float inv = 1.f / s;
    v0.x *= inv; v0.y *= inv; v0.z *= inv; v0.w *= inv;
    v1.x *= inv; v1.y *= inv; v1.z *= inv; v1.w *= inv;
    p[threadIdx.x] = v0;
    p[threadIdx.x + 256] = v1;
}

// ---------------- generic 128x128x16 SGEMM (fp32 via packed f32x2) ----------
// C[m,n] = alpha * sum_k A[m,k] * (TRANSB ? B[n,k] : B[k,n])   (+ Cadd[m,n])
// batched over z: b=z/H, h=z%H with per-b/per-h element strides.
template <int TRANSB, int ADDC>
__global__ __launch_bounds__(256, 2)
void sgemm_k(const float* __restrict__ A, const float* __restrict__ B,
             const float* __restrict__ Cadd, float* __restrict__ C,
             int K, int lda, int ldb, int ldc,
             long long sAb, long long sAh, long long sBb, long long sBh,
             long long sCb, long long sCh, int H, float alpha) {
    __shared__ float As[16][128];
    __shared__ float Bs[16][132];   // 528B rows: 16B-aligned for float4 & u64

    int z = blockIdx.z;
    int bb = z / H, hh = z - bb * H;
    A += bb * sAb + hh * sAh;
    B += bb * sBb + hh * sBh;
    C += bb * sCb + hh * sCh;
    if (ADDC) Cadd += bb * sCb + hh * sCh;

    int row0 = blockIdx.y * 128;
    int col0 = blockIdx.x * 128;
    int tid = threadIdx.x;
    int tx = tid & 15, ty = tid >> 4;

    unsigned long long acc[8][4];
    #pragma unroll
    for (int i = 0; i < 8; i++)
        #pragma unroll
        for (int j = 0; j < 4; j++) acc[i][j] = 0ULL;

    for (int k0 = 0; k0 < K; k0 += 16) {
        // A tile: 128 rows x 16 k, store transposed As[k][m]
        #pragma unroll
        for (int i = 0; i < 2; i++) {
            int idx = tid * 2 + i;
            int ar = idx >> 2, k4 = (idx & 3) << 2;
            float4 va = *(const float4*)(A + (long long)(row0 + ar) * lda + k0 + k4);
            As[k4 + 0][ar] = va.x; As[k4 + 1][ar] = va.y;
            As[k4 + 2][ar] = va.z; As[k4 + 3][ar] = va.w;
        }
        if (TRANSB) {
            #pragma unroll
            for (int i = 0; i < 2; i++) {
                int idx = tid * 2 + i;
                int br = idx >> 2, k4 = (idx & 3) << 2;
                float4 vb = *(const float4*)(B + (long long)(col0 + br) * ldb + k0 + k4);
                Bs[k4 + 0][br] = vb.x; Bs[k4 + 1][br] = vb.y;
                Bs[k4 + 2][br] = vb.z; Bs[k4 + 3][br] = vb.w;
            }
        } else {
            #pragma unroll
            for (int i = 0; i < 2; i++) {
                int idx = tid * 2 + i;
                int bk = idx >> 5, n4 = (idx & 31) << 2;
                float4 vb = *(const float4*)(B + (long long)(k0 + bk) * ldb + col0 + n4);
                *(float4*)&Bs[bk][n4] = vb;
            }
        }
        __syncthreads();

        #pragma unroll
        for (int k = 0; k < 16; k++) {
            float4 a0 = *(const float4*)&As[k][ty * 4];
            float4 a1 = *(const float4*)&As[k][64 + ty * 4];
            unsigned long long bp[4];
            bp[0] = *(const unsigned long long*)&Bs[k][tx * 4];
            bp[1] = *(const unsigned long long*)&Bs[k][tx * 4 + 2];
            bp[2] = *(const unsigned long long*)&Bs[k][64 + tx * 4];
            bp[3] = *(const unsigned long long*)&Bs[k][64 + tx * 4 + 2];
            unsigned long long ap[8];
            ap[0] = pack_dup(a0.x); ap[1] = pack_dup(a0.y);
            ap[2] = pack_dup(a0.z); ap[3] = pack_dup(a0.w);
            ap[4] = pack_dup(a1.x); ap[5] = pack_dup(a1.y);
            ap[6] = pack_dup(a1.z); ap[7] = pack_dup(a1.w);
            #pragma unroll
            for (int i = 0; i < 8; i++)
                #pragma unroll
                for (int j = 0; j < 4; j++) ffma2(acc[i][j], ap[i], bp[j]);
        }
        __syncthreads();
    }

    // epilogue
    #pragma unroll
    for (int i = 0; i < 8; i++) {
        int m = row0 + ((i < 4) ? (ty * 4 + i) : (64 + ty * 4 + i - 4));
        #pragma unroll
        for (int j = 0; j < 4; j++) {
            int n = col0 + ((j < 2) ? (tx * 4 + j * 2) : (64 + tx * 4 + (j - 2) * 2));
            float2 v = unpack2(acc[i][j]);
            v.x *= alpha; v.y *= alpha;
            if (ADDC) {
                float2 cv = *(const float2*)(Cadd + (long long)m * ldc + n);
                v.x += cv.x; v.y += cv.y;
            }
            *(float2*)(C + (long long)m * ldc + n) = v;
        }
    }
}

// ---------------------------------------------------------------------------
extern "C" void kernel_launch(void* const* d_in, const int* in_sizes, int n_in,
                              void* d_out, int out_size) {
    const float* x      = (const float*)d_in[0];
    const float* emb    = (const float*)d_in[1];
    const float* W_emb  = (const float*)d_in[2];
    const float* b_emb  = (const float*)d_in[3];
    const float* g_norm = (const float*)d_in[4];
    const float* W_qkv  = (const float*)d_in[5];
    const float* g_q    = (const float*)d_in[6];
    const float* g_k    = (const float*)d_in[7];
    const float* W_out  = (const float*)d_in[8];
    float* out = (float*)d_out;
    (void)in_sizes; (void)n_in; (void)out_size;

    float *ss, *xn, *qkv, *logits, *otok;
    cudaGetSymbolAddress((void**)&ss,     g_ss);
    cudaGetSymbolAddress((void**)&xn,     g_xn);
    cudaGetSymbolAddress((void**)&qkv,    g_qkv);
    cudaGetSymbolAddress((void**)&logits, g_logits);
    cudaGetSymbolAddress((void**)&otok,   g_otok);

    const float att_scale = 0.08838834764831845f;   // 1/sqrt(128)

    // 1) scale/shift
    k_scale_shift<<<dim3((2 * DIM_) / 256, B_), 256>>>(emb, W_emb, b_emb, ss);

    // 2) AdaLN RMSNorm
    k_xnorm<<<TOK_, 256>>>(x, g_norm, ss, xn);

    // 3) QKV GEMM: [8192,2048] x [2048,6144]
    sgemm_k<0, 0><<<dim3(QKVC_ / 128, TOK_ / 128, 1), 256>>>(
        xn, W_qkv, nullptr, qkv, DIM_, DIM_, QKVC_, QKVC_,
        0, 0, 0, 0, 0, 0, 1, 1.0f);

    // 4) per-head q/k RMSNorm
    k_qknorm<<<TOK_, 512>>>(qkv, g_q, g_k);

    // 5) logits = q @ k^T * scale   (NT, batched over b*h)
    sgemm_k<1, 0><<<dim3(N_ / 128, N_ / 128, B_ * H_), 256>>>(
        qkv,            /* q at col 0   */
        qkv + DIM_,     /* k at col 2048 */
        nullptr, logits, DH_, QKVC_, QKVC_, N_,
        (long long)N_ * QKVC_, DH_,
        (long long)N_ * QKVC_, DH_,
        (long long)H_ * N_ * N_, (long long)N_ * N_,
        H_, att_scale);

    // 6) softmax rows
    k_softmax<<<B_ * H_ * N_, 256>>>(logits);

    // 7) o = attn @ v  -> token-major [8192, 2048]
    sgemm_k<0, 0><<<dim3(1, N_ / 128, B_ * H_), 256>>>(
        logits,
        qkv + 2 * DIM_, /* v at col 4096 */
        nullptr, otok, N_, N_, QKVC_, DIM_,
        (long long)H_ * N_ * N_, (long long)N_ * N_,
        (long long)N_ * QKVC_, DH_,
        (long long)N_ * DIM_, DH_,
        H_, 1.0f);

    // 8) out = o + o @ W_out
    sgemm_k<0, 1><<<dim3(DIM_ / 128, TOK_ / 128, 1), 256>>>(
        otok, W_out, otok, out, DIM_, DIM_, DIM_, DIM_,
        0, 0, 0, 0, 0, 0, 1, 1.0f);
}

// round 3
// speedup vs baseline: 1.6804x; 1.6804x over previous
#include <cuda_runtime.h>
#include <cuda_bf16.h>
#include <cstdint>

// ---------------------------------------------------------------------------
// AttentionBlock: b=4, n=2048, dim=2048, heads=16, d_head=128  (fp32 I/O)
// GEMMs: mma.sync.m16n8k16 bf16 with 3-term hi/lo split (fp32-accurate).
// (tcgen05 is unavailable: harness PTX targets compute_103, not compute_103a)
// ---------------------------------------------------------------------------

#define B_     4
#define N_     2048
#define DIM_   2048
#define H_     16
#define DH_    128
#define TOK_   (B_ * N_)          // 8192
#define QKVC_  (3 * DIM_)         // 6144
#define BH_    (B_ * H_)          // 64

// ---------------- scratch (__device__ globals: sanctioned no-alloc path) ----
__device__ float          g_ss[B_ * 2 * DIM_];
__device__ __nv_bfloat16  g_xnh[(long long)TOK_ * DIM_];
__device__ __nv_bfloat16  g_xnl[(long long)TOK_ * DIM_];
__device__ __nv_bfloat16  g_wqTh[(long long)QKVC_ * DIM_];
__device__ __nv_bfloat16  g_wqTl[(long long)QKVC_ * DIM_];
__device__ __nv_bfloat16  g_woTh[(long long)DIM_ * DIM_];
__device__ __nv_bfloat16  g_woTl[(long long)DIM_ * DIM_];
__device__ float          g_qkv[(long long)TOK_ * QKVC_];
__device__ __nv_bfloat16  g_qkh[(long long)TOK_ * 2 * DIM_];
__device__ __nv_bfloat16  g_qkl[(long long)TOK_ * 2 * DIM_];
__device__ __nv_bfloat16  g_vTh[(long long)BH_ * DH_ * N_];
__device__ __nv_bfloat16  g_vTl[(long long)BH_ * DH_ * N_];
__device__ float          g_logits[(long long)BH_ * N_ * N_];
__device__ __nv_bfloat16  g_ah[(long long)BH_ * N_ * N_];
__device__ __nv_bfloat16  g_al[(long long)BH_ * N_ * N_];
__device__ float          g_otok[(long long)TOK_ * DIM_];
__device__ __nv_bfloat16  g_oh[(long long)TOK_ * DIM_];
__device__ __nv_bfloat16  g_ol[(long long)TOK_ * DIM_];

// ---------------- PTX helpers ------------------------------------------------
__device__ __forceinline__ uint32_t smem_u32(const void* p) {
    uint32_t a;
    asm("{ .reg .u64 t; cvta.to.shared.u64 t, %1; cvt.u32.u64 %0, t; }"
        : "=r"(a) : "l"(p));
    return a;
}
__device__ __forceinline__ void cp16(uint32_t dst, const void* src) {
    asm volatile("cp.async.cg.shared.global [%0], [%1], 16;"
                 :: "r"(dst), "l"(__cvta_generic_to_global(src)));
}
__device__ __forceinline__ void cp_commit() {
    asm volatile("cp.async.commit_group;" ::: "memory");
}
template <int NN>
__device__ __forceinline__ void cp_wait() {
    asm volatile("cp.async.wait_group %0;" :: "n"(NN) : "memory");
}
__device__ __forceinline__ void ldsm4(uint32_t& r0, uint32_t& r1,
                                      uint32_t& r2, uint32_t& r3, uint32_t a) {
    asm volatile("ldmatrix.sync.aligned.m8n8.x4.shared.b16 {%0,%1,%2,%3}, [%4];"
                 : "=r"(r0), "=r"(r1), "=r"(r2), "=r"(r3) : "r"(a));
}
__device__ __forceinline__ void mma16816(float* d, const uint32_t* a,
                                         const uint32_t* b) {
    asm volatile(
        "mma.sync.aligned.m16n8k16.row.col.f32.bf16.bf16.f32 "
        "{%0,%1,%2,%3}, {%4,%5,%6,%7}, {%8,%9}, {%0,%1,%2,%3};"
        : "+f"(d[0]), "+f"(d[1]), "+f"(d[2]), "+f"(d[3])
        : "r"(a[0]), "r"(a[1]), "r"(a[2]), "r"(a[3]), "r"(b[0]), "r"(b[1]));
}

// ---------------- fp32 -> bf16 hi/lo split ----------------------------------
__device__ __forceinline__ void split_store4(float4 v,
                                             __nv_bfloat16* __restrict__ hi,
                                             __nv_bfloat16* __restrict__ lo) {
    __nv_bfloat16 h[4], l[4];
    float f[4] = {v.x, v.y, v.z, v.w};
    #pragma unroll
    for (int i = 0; i < 4; i++) {
        h[i] = __float2bfloat16(f[i]);
        l[i] = __float2bfloat16(f[i] - __bfloat162float(h[i]));
    }
    *(uint2*)hi = *(const uint2*)h;
    *(uint2*)lo = *(const uint2*)l;
}

// ---------------- block reductions ------------------------------------------
__device__ __forceinline__ float blk_sum256(float v) {
    __shared__ float red[8];
    __shared__ float tot;
    #pragma unroll
    for (int o = 16; o > 0; o >>= 1) v += __shfl_xor_sync(0xffffffffu, v, o);
    if ((threadIdx.x & 31) == 0) red[threadIdx.x >> 5] = v;
    __syncthreads();
    if (threadIdx.x == 0) {
        float s = 0.f;
        #pragma unroll
        for (int i = 0; i < 8; i++) s += red[i];
        tot = s;
    }
    __syncthreads();
    return tot;
}
__device__ __forceinline__ float blk_max256(float v) {
    __shared__ float red[8];
    __shared__ float tot;
    #pragma unroll
    for (int o = 16; o > 0; o >>= 1) v = fmaxf(v, __shfl_xor_sync(0xffffffffu, v, o));
    if ((threadIdx.x & 31) == 0) red[threadIdx.x >> 5] = v;
    __syncthreads();
    if (threadIdx.x == 0) {
        float s = red[0];
        #pragma unroll
        for (int i = 1; i < 8; i++) s = fmaxf(s, red[i]);
        tot = s;
    }
    __syncthreads();
    return tot;
}

// ---------------- K1: scale_shift = emb @ W_emb + b_emb ---------------------
__global__ void k_scale_shift(const float* __restrict__ emb,
                              const float* __restrict__ W,
                              const float* __restrict__ bias,
                              float* __restrict__ ss) {
    int c = blockIdx.x * 256 + threadIdx.x;
    int b = blockIdx.y;
    const float* e = emb + b * DIM_;
    float acc = bias[c];
    const float* wp = W + c;
    #pragma unroll 8
    for (int k = 0; k < DIM_; k++)
        acc = fmaf(e[k], wp[(long long)k * (2 * DIM_)], acc);
    ss[b * (2 * DIM_) + c] = acc;
}

// ---------------- K2: xn = RMSNorm(x)*g*(1+scale)+shift  -> hi/lo bf16 ------
__global__ void k_xnorm(const float* __restrict__ x,
                        const float* __restrict__ g,
                        const float* __restrict__ ss,
                        __nv_bfloat16* __restrict__ xh,
                        __nv_bfloat16* __restrict__ xl) {
    long long row = blockIdx.x;
    int b = (int)(row >> 11);
    const float4* xr = (const float4*)(x + row * DIM_);
    float4 v0 = xr[threadIdx.x];
    float4 v1 = xr[threadIdx.x + 256];
    float s = v0.x * v0.x + v0.y * v0.y + v0.z * v0.z + v0.w * v0.w
            + v1.x * v1.x + v1.y * v1.y + v1.z * v1.z + v1.w * v1.w;
    s = blk_sum256(s);
    float r = rsqrtf(s * (1.f / DIM_) + 1e-6f);
    const float* sc = ss + b * (2 * DIM_);
    const float* sh = sc + DIM_;
    int c0 = threadIdx.x * 4;
    int c1 = (threadIdx.x + 256) * 4;
    float4 o0, o1;
    o0.x = fmaf(v0.x * r * g[c0 + 0], 1.f + sc[c0 + 0], sh[c0 + 0]);
    o0.y = fmaf(v0.y * r * g[c0 + 1], 1.f + sc[c0 + 1], sh[c0 + 1]);
    o0.z = fmaf(v0.z * r * g[c0 + 2], 1.f + sc[c0 + 2], sh[c0 + 2]);
    o0.w = fmaf(v0.w * r * g[c0 + 3], 1.f + sc[c0 + 3], sh[c0 + 3]);
    o1.x = fmaf(v1.x * r * g[c1 + 0], 1.f + sc[c1 + 0], sh[c1 + 0]);
    o1.y = fmaf(v1.y * r * g[c1 + 1], 1.f + sc[c1 + 1], sh[c1 + 1]);
    o1.z = fmaf(v1.z * r * g[c1 + 2], 1.f + sc[c1 + 2], sh[c1 + 2]);
    o1.w = fmaf(v1.w * r * g[c1 + 3], 1.f + sc[c1 + 3], sh[c1 + 3]);
    long long base = row * DIM_;
    split_store4(o0, xh + base + c0, xl + base + c0);
    split_store4(o1, xh + base + c1, xl + base + c1);
}

// ---------------- K3: transpose + split weights  W[KR,NC] -> T[NC,KR] -------
__global__ void k_tsplit(const float* __restrict__ W, int KR, int NC,
                         __nv_bfloat16* __restrict__ Th,
                         __nv_bfloat16* __restrict__ Tl) {
    __shared__ float t[32][33];
    int c0 = blockIdx.x * 32;
    int r0 = blockIdx.y * 32;
    for (int i = threadIdx.y; i < 32; i += 8)
        t[i][threadIdx.x] = W[(long long)(r0 + i) * NC + c0 + threadIdx.x];
    __syncthreads();
    for (int i = threadIdx.y; i < 32; i += 8) {
        float v = t[threadIdx.x][i];
        long long o = (long long)(c0 + i) * KR + r0 + threadIdx.x;
        __nv_bfloat16 h = __float2bfloat16(v);
        Th[o] = h;
        Tl[o] = __float2bfloat16(v - __bfloat162float(h));
    }
}

// ---------------- K5: per-head q/k RMSNorm + split --------------------------
__global__ void k_qknorm_split(const float* __restrict__ qkv,
                               const float* __restrict__ gq,
                               const float* __restrict__ gk,
                               __nv_bfloat16* __restrict__ qh,
                               __nv_bfloat16* __restrict__ ql) {
    int row = blockIdx.x;
    int h = threadIdx.x >> 5;
    int lane = threadIdx.x & 31;
    const float* q = qkv + (long long)row * QKVC_ + h * DH_;
    const float* k = q + DIM_;
    long long qo = (long long)row * (2 * DIM_) + h * DH_ + lane * 4;
    {
        float4 v = *(const float4*)(q + lane * 4);
        float s = v.x * v.x + v.y * v.y + v.z * v.z + v.w * v.w;
        #pragma unroll
        for (int o = 16; o > 0; o >>= 1) s += __shfl_xor_sync(0xffffffffu, s, o);
        float r = rsqrtf(s * (1.f / DH_) + 1e-6f);
        v.x *= r * gq[lane * 4 + 0]; v.y *= r * gq[lane * 4 + 1];
        v.z *= r * gq[lane * 4 + 2]; v.w *= r * gq[lane * 4 + 3];
        split_store4(v, qh + qo, ql + qo);
    }
    {
        float4 v = *(const float4*)(k + lane * 4);
        float s = v.x * v.x + v.y * v.y + v.z * v.z + v.w * v.w;
        #pragma unroll
        for (int o = 16; o > 0; o >>= 1) s += __shfl_xor_sync(0xffffffffu, s, o);
        float r = rsqrtf(s * (1.f / DH_) + 1e-6f);
        v.x *= r * gk[lane * 4 + 0]; v.y *= r * gk[lane * 4 + 1];
        v.z *= r * gk[lane * 4 + 2]; v.w *= r * gk[lane * 4 + 3];
        split_store4(v, qh + qo + DIM_, ql + qo + DIM_);
    }
}

// ---------------- K5b: v -> vT per head, split ------------------------------
__global__ void k_vsplit(const float* __restrict__ qkv,
                         __nv_bfloat16* __restrict__ vh,
                         __nv_bfloat16* __restrict__ vl) {
    __shared__ float t[32][33];
    int z = blockIdx.z, b = z >> 4, h = z & 15;
    int s0 = blockIdx.x * 32, d0 = blockIdx.y * 32;
    const float* src = qkv + (long long)b * N_ * QKVC_ + 2 * DIM_ + h * DH_;
    for (int i = threadIdx.y; i < 32; i += 8)
        t[i][threadIdx.x] = src[(long long)(s0 + i) * QKVC_ + d0 + threadIdx.x];
    __syncthreads();
    long long ob = (long long)z * DH_ * N_;
    for (int i = threadIdx.y; i < 32; i += 8) {
        float v = t[threadIdx.x][i];
        long long o = ob + (long long)(d0 + i) * N_ + s0 + threadIdx.x;
        __nv_bfloat16 hh = __float2bfloat16(v);
        vh[o] = hh;
        vl[o] = __float2bfloat16(v - __bfloat162float(hh));
    }
}

// ---------------- K7: softmax rows -> attn hi/lo bf16 -----------------------
__global__ void k_softmax_split(const float* __restrict__ logits,
                                __nv_bfloat16* __restrict__ ah,
                                __nv_bfloat16* __restrict__ al) {
    long long row = blockIdx.x;
    const float4* p = (const float4*)(logits + row * (long long)N_);
    float4 v0 = p[threadIdx.x];
    float4 v1 = p[threadIdx.x + 256];
    float mx = fmaxf(fmaxf(fmaxf(v0.x, v0.y), fmaxf(v0.z, v0.w)),
                     fmaxf(fmaxf(v1.x, v1.y), fmaxf(v1.z, v1.w)));
    mx = blk_max256(mx);
    v0.x = __expf(v0.x - mx); v0.y = __expf(v0.y - mx);
    v0.z = __expf(v0.z - mx); v0.w = __expf(v0.w - mx);
    v1.x = __expf(v1.x - mx); v1.y = __expf(v1.y - mx);
    v1.z = __expf(v1.z - mx); v1.w = __expf(v1.w - mx);
    float s = v0.x + v0.y + v0.z + v0.w + v1.x + v1.y + v1.z + v1.w;
    s = blk_sum256(s);
    float inv = 1.f / s;
    v0.x *= inv; v0.y *= inv; v0.z *= inv; v0.w *= inv;
    v1.x *= inv; v1.y *= inv; v1.z *= inv; v1.w *= inv;
    long long base = row * (long long)N_;
    split_store4(v0, ah + base + threadIdx.x * 4, al + base + threadIdx.x * 4);
    split_store4(v1, ah + base + (threadIdx.x + 256) * 4,
                     al + base + (threadIdx.x + 256) * 4);
}

// ---------------- K9: split o_tok -> hi/lo ----------------------------------
__global__ void k_split4(const float* __restrict__ src,
                         __nv_bfloat16* __restrict__ hi,
                         __nv_bfloat16* __restrict__ lo, long long n4) {
    long long i = (long long)blockIdx.x * blockDim.x + threadIdx.x;
    if (i < n4) {
        float4 v = ((const float4*)src)[i];
        split_store4(v, hi + i * 4, lo + i * 4);
    }
}

// ---------------------------------------------------------------------------
// mma.sync bf16x3 GEMM:  C = alpha * (Ahi+Alo)(Bhi+Blo)^T  (+ Cadd)
//   A [M,K] K-major hi/lo, B [N,K] K-major hi/lo, C fp32 [M,N].
//   Block tile 128x128, 8 warps (warp tile 64x32), K-chunk 32,
//   3-stage cp.async pipeline, 80B-padded rows (conflict-free ldmatrix).
// ---------------------------------------------------------------------------
#define ROWB   80
#define TILEB  (128 * ROWB)        // 10240 B
#define STAGEB (4 * TILEB)         // 40960 B
#define NSTAGE 3
#define GEMM_SMEM (NSTAGE * STAGEB) // 122880 B

__global__ void __launch_bounds__(256, 1)
gemm_bf16x3(const __nv_bfloat16* __restrict__ Ahi, const __nv_bfloat16* __restrict__ Alo,
            int lda,
            const __nv_bfloat16* __restrict__ Bhi, const __nv_bfloat16* __restrict__ Blo,
            int ldb,
            const float* __restrict__ Cadd, float* __restrict__ C, int ldc,
            int K,
            long long sAb, long long sAh, long long sBb, long long sBh,
            long long sCb, long long sCh, int H, float alpha) {
    extern __shared__ char smem[];
    uint32_t sb = smem_u32(smem);
    int tid = threadIdx.x;
    int wid = tid >> 5, lane = tid & 31;
    int warp_m = wid >> 2;     // 0..1  -> 64 rows each
    int warp_n = wid & 3;      // 0..3  -> 32 cols each

    int z = blockIdx.z;
    int bb = z / H, hh = z - bb * H;
    long long aoff = bb * sAb + hh * sAh;
    long long boff = bb * sBb + hh * sBh;
    long long coff = bb * sCb + hh * sCh;
    Ahi += aoff; Alo += aoff;
    Bhi += boff; Blo += boff;
    C += coff;
    if (Cadd) Cadd += coff;

    int row0 = blockIdx.y * 128;
    int col0 = blockIdx.x * 128;

    float acc[4][4][4];
    #pragma unroll
    for (int i = 0; i < 4; i++)
        #pragma unroll
        for (int j = 0; j < 4; j++)
            #pragma unroll
            for (int r = 0; r < 4; r++) acc[i][j][r] = 0.f;

    int NC = K >> 5;

    // ---- stage loader --------------------------------------------------
    auto load_stage = [&](int slot, int k0) {
        uint32_t base = sb + slot * STAGEB;
        #pragma unroll
        for (int j = 0; j < 8; j++) {
            int id  = tid + j * 256;
            int t   = id >> 9;            // 0:Ahi 1:Alo 2:Bhi 3:Blo
            int rid = (id >> 2) & 127;    // row within tile
            int seg = id & 3;             // 16B segment (8 bf16)
            uint32_t dst = base + (uint32_t)t * TILEB + (uint32_t)rid * ROWB + seg * 16;
            const __nv_bfloat16* p = (t < 2) ? ((t == 0) ? Ahi : Alo)
                                             : ((t == 2) ? Bhi : Blo);
            int r0g = (t < 2) ? row0 : col0;
            int ld  = (t < 2) ? lda : ldb;
            cp16(dst, p + (long long)(r0g + rid) * ld + k0 + seg * 8);
        }
        cp_commit();
    };

    load_stage(0, 0);
    if (NC > 1) load_stage(1, 32);
    else        cp_commit();   // keep group count consistent

    int lr = lane & 15;                 // ldmatrix row within 16
    uint32_t lc = ((lane >> 4) << 4);   // 0 / 16 bytes (k8 half)

    for (int i = 0; i < NC; i++) {
        if (i < NC - 1) cp_wait<1>();
        else            cp_wait<0>();
        __syncthreads();

        int slot = i % NSTAGE;
        uint32_t abase = sb + slot * STAGEB + (uint32_t)(warp_m * 64 + lr) * ROWB + lc;
        uint32_t bbase = sb + slot * STAGEB + 2 * TILEB
                       + (uint32_t)(warp_n * 32 + lr) * ROWB + lc;

        #pragma unroll
        for (int s = 0; s < 2; s++) {
            uint32_t koff = s * 32;
            uint32_t Ah[4][4], Al[4][4], Bh[4][2], Bl[4][2];
            #pragma unroll
            for (int mi = 0; mi < 4; mi++) {
                uint32_t a = abase + (uint32_t)(mi * 16) * ROWB + koff;
                ldsm4(Ah[mi][0], Ah[mi][1], Ah[mi][2], Ah[mi][3], a);
                ldsm4(Al[mi][0], Al[mi][1], Al[mi][2], Al[mi][3], a + TILEB);
            }
            #pragma unroll
            for (int np = 0; np < 2; np++) {
                uint32_t a = bbase + (uint32_t)(np * 16) * ROWB + koff;
                uint32_t r0, r1, r2, r3;
                ldsm4(r0, r1, r2, r3, a);
                Bh[2 * np][0] = r0; Bh[2 * np][1] = r2;
                Bh[2 * np + 1][0] = r1; Bh[2 * np + 1][1] = r3;
                ldsm4(r0, r1, r2, r3, a + TILEB);
                Bl[2 * np][0] = r0; Bl[2 * np][1] = r2;
                Bl[2 * np + 1][0] = r1; Bl[2 * np + 1][1] = r3;
            }
            #pragma unroll
            for (int mi = 0; mi < 4; mi++)
                #pragma unroll
                for (int ni = 0; ni < 4; ni++) {
                    mma16816(acc[mi][ni], Ah[mi], Bh[ni]);
                    mma16816(acc[mi][ni], Ah[mi], Bl[ni]);
                    mma16816(acc[mi][ni], Al[mi], Bh[ni]);
                }
        }
        __syncthreads();
        if (i + 2 < NC) load_stage((i + 2) % NSTAGE, (i + 2) * 32);
    }

    // ---- epilogue ------------------------------------------------------
    bool addc = (Cadd != nullptr);
    int mrow = row0 + warp_m * 64 + (lane >> 2);
    int ccol = col0 + warp_n * 32 + (lane & 3) * 2;
    #pragma unroll
    for (int mi = 0; mi < 4; mi++) {
        #pragma unroll
        for (int ni = 0; ni < 4; ni++) {
            long long o0 = (long long)(mrow + mi * 16) * ldc + ccol + ni * 8;
            long long o1 = o0 + 8LL * ldc;
            float2 v0 = make_float2(acc[mi][ni][0] * alpha, acc[mi][ni][1] * alpha);
            float2 v1 = make_float2(acc[mi][ni][2] * alpha, acc[mi][ni][3] * alpha);
            if (addc) {
                float2 c0 = *(const float2*)(Cadd + o0);
                float2 c1 = *(const float2*)(Cadd + o1);
                v0.x += c0.x; v0.y += c0.y;
                v1.x += c1.x; v1.y += c1.y;
            }
            *(float2*)(C + o0) = v0;
            *(float2*)(C + o1) = v1;
        }
    }
}

// ---------------------------------------------------------------------------
extern "C" void kernel_launch(void* const* d_in, const int* in_sizes, int n_in,
                              void* d_out, int out_size) {
    const float* x      = (const float*)d_in[0];
    const float* emb    = (const float*)d_in[1];
    const float* W_emb  = (const float*)d_in[2];
    const float* b_emb  = (const float*)d_in[3];
    const float* g_norm = (const float*)d_in[4];
    const float* W_qkv  = (const float*)d_in[5];
    const float* g_q    = (const float*)d_in[6];
    const float* g_k    = (const float*)d_in[7];
    const float* W_out  = (const float*)d_in[8];
    float* out = (float*)d_out;
    (void)in_sizes; (void)n_in; (void)out_size;

    float *ss, *qkv, *logits, *otok;
    __nv_bfloat16 *xnh, *xnl, *wqTh, *wqTl, *woTh, *woTl;
    __nv_bfloat16 *qkh, *qkl, *vTh, *vTl, *ah, *al, *oh, *ol;
    cudaGetSymbolAddress((void**)&ss,     g_ss);
    cudaGetSymbolAddress((void**)&xnh,    g_xnh);
    cudaGetSymbolAddress((void**)&xnl,    g_xnl);
    cudaGetSymbolAddress((void**)&wqTh,   g_wqTh);
    cudaGetSymbolAddress((void**)&wqTl,   g_wqTl);
    cudaGetSymbolAddress((void**)&woTh,   g_woTh);
    cudaGetSymbolAddress((void**)&woTl,   g_woTl);
    cudaGetSymbolAddress((void**)&qkv,    g_qkv);
    cudaGetSymbolAddress((void**)&qkh,    g_qkh);
    cudaGetSymbolAddress((void**)&qkl,    g_qkl);
    cudaGetSymbolAddress((void**)&vTh,    g_vTh);
    cudaGetSymbolAddress((void**)&vTl,    g_vTl);
    cudaGetSymbolAddress((void**)&logits, g_logits);
    cudaGetSymbolAddress((void**)&ah,     g_ah);
    cudaGetSymbolAddress((void**)&al,     g_al);
    cudaGetSymbolAddress((void**)&otok,   g_otok);
    cudaGetSymbolAddress((void**)&oh,     g_oh);
    cudaGetSymbolAddress((void**)&ol,     g_ol);

    cudaFuncSetAttribute(gemm_bf16x3,
                         cudaFuncAttributeMaxDynamicSharedMemorySize, GEMM_SMEM);

    const float att_scale = 0.08838834764831845f;   // 1/sqrt(128)

    // 1) scale/shift
    k_scale_shift<<<dim3((2 * DIM_) / 256, B_), 256>>>(emb, W_emb, b_emb, ss);

    // 2) AdaLN RMSNorm -> xn hi/lo
    k_xnorm<<<TOK_, 256>>>(x, g_norm, ss, xnh, xnl);

    // 3) transpose + split weights
    k_tsplit<<<dim3(QKVC_ / 32, DIM_ / 32), dim3(32, 8)>>>(W_qkv, DIM_, QKVC_, wqTh, wqTl);
    k_tsplit<<<dim3(DIM_ / 32, DIM_ / 32),  dim3(32, 8)>>>(W_out, DIM_, DIM_, woTh, woTl);

    // 4) QKV GEMM: [8192,2048] x [2048,6144] -> qkv fp32
    gemm_bf16x3<<<dim3(QKVC_ / 128, TOK_ / 128, 1), 256, GEMM_SMEM>>>(
        xnh, xnl, DIM_, wqTh, wqTl, DIM_, nullptr, qkv, QKVC_,
        DIM_, 0, 0, 0, 0, 0, 0, 1, 1.0f);

    // 5) per-head q/k RMSNorm + split; v transpose + split
    k_qknorm_split<<<TOK_, 512>>>(qkv, g_q, g_k, qkh, qkl);
    k_vsplit<<<dim3(N_ / 32, DH_ / 32, BH_), dim3(32, 8)>>>(qkv, vTh, vTl);

    // 6) logits = q @ k^T * scale  (batched bh)
    gemm_bf16x3<<<dim3(N_ / 128, N_ / 128, BH_), 256, GEMM_SMEM>>>(
        qkh, qkl, 2 * DIM_, qkh + DIM_, qkl + DIM_, 2 * DIM_, nullptr, logits, N_,
        DH_,
        (long long)N_ * 2 * DIM_, DH_,
        (long long)N_ * 2 * DIM_, DH_,
        (long long)H_ * N_ * N_, (long long)N_ * N_,
        H_, att_scale);

    // 7) softmax -> attn hi/lo
    k_softmax_split<<<BH_ * N_, 256>>>(logits, ah, al);

    // 8) o = attn @ v  -> token-major otok fp32
    gemm_bf16x3<<<dim3(1, N_ / 128, BH_), 256, GEMM_SMEM>>>(
        ah, al, N_, vTh, vTl, N_, nullptr, otok, DIM_,
        N_,
        (long long)H_ * N_ * N_, (long long)N_ * N_,
        (long long)H_ * DH_ * N_, (long long)DH_ * N_,
        (long long)N_ * DIM_, (long long)DH_,
        H_, 1.0f);

    // 9) split o
    k_split4<<<(int)(((long long)TOK_ * DIM_ / 4 + 255) / 256), 256>>>(
        otok, oh, ol, (long long)TOK_ * DIM_ / 4);

    // 10) out = o + o @ W_out
    gemm_bf16x3<<<dim3(DIM_ / 128, TOK_ / 128, 1), 256, GEMM_SMEM>>>(
        oh, ol, DIM_, woTh, woTl, DIM_, otok, out, DIM_,
        DIM_, 0, 0, 0, 0, 0, 0, 1, 1.0f);
}

// round 5
// speedup vs baseline: 1.8138x; 1.0794x over previous
#include <cuda_runtime.h>
#include <cuda_bf16.h>
#include <cstdint>

// ---------------------------------------------------------------------------
// AttentionBlock: b=4, n=2048, dim=2048, heads=16, d_head=128  (fp32 I/O)
// GEMMs: mma.sync.m16n8k16 bf16 with 3-term hi/lo split (fp32-accurate).
// ---------------------------------------------------------------------------

#define B_     4
#define N_     2048
#define DIM_   2048
#define H_     16
#define DH_    128
#define TOK_   (B_ * N_)          // 8192
#define QKVC_  (3 * DIM_)         // 6144
#define BH_    (B_ * H_)          // 64

// ---------------- scratch (__device__ globals) ------------------------------
__device__ float          g_ss[B_ * 2 * DIM_];
__device__ __nv_bfloat16  g_xnh[(long long)TOK_ * DIM_];
__device__ __nv_bfloat16  g_xnl[(long long)TOK_ * DIM_];
__device__ __nv_bfloat16  g_wqTh[(long long)QKVC_ * DIM_];
__device__ __nv_bfloat16  g_wqTl[(long long)QKVC_ * DIM_];
__device__ __nv_bfloat16  g_woTh[(long long)DIM_ * DIM_];
__device__ __nv_bfloat16  g_woTl[(long long)DIM_ * DIM_];
__device__ float          g_qkv[(long long)TOK_ * QKVC_];
__device__ __nv_bfloat16  g_qkh[(long long)TOK_ * 2 * DIM_];
__device__ __nv_bfloat16  g_qkl[(long long)TOK_ * 2 * DIM_];
__device__ __nv_bfloat16  g_vTh[(long long)BH_ * DH_ * N_];
__device__ __nv_bfloat16  g_vTl[(long long)BH_ * DH_ * N_];
__device__ float          g_logits[(long long)BH_ * N_ * N_];
__device__ __nv_bfloat16  g_ah[(long long)BH_ * N_ * N_];
__device__ __nv_bfloat16  g_al[(long long)BH_ * N_ * N_];
__device__ float          g_otok[(long long)TOK_ * DIM_];
__device__ __nv_bfloat16  g_oh[(long long)TOK_ * DIM_];
__device__ __nv_bfloat16  g_ol[(long long)TOK_ * DIM_];

// ---------------- PTX helpers ------------------------------------------------
__device__ __forceinline__ uint32_t smem_u32(const void* p) {
    uint32_t a;
    asm("{ .reg .u64 t; cvta.to.shared.u64 t, %1; cvt.u32.u64 %0, t; }"
        : "=r"(a) : "l"(p));
    return a;
}
__device__ __forceinline__ void cp16(uint32_t dst, const void* src) {
    asm volatile("cp.async.cg.shared.global [%0], [%1], 16;"
                 :: "r"(dst), "l"(__cvta_generic_to_global(src)));
}
__device__ __forceinline__ void cp_commit() {
    asm volatile("cp.async.commit_group;" ::: "memory");
}
template <int NN>
__device__ __forceinline__ void cp_wait() {
    asm volatile("cp.async.wait_group %0;" :: "n"(NN) : "memory");
}
__device__ __forceinline__ void ldsm4(uint32_t& r0, uint32_t& r1,
                                      uint32_t& r2, uint32_t& r3, uint32_t a) {
    asm volatile("ldmatrix.sync.aligned.m8n8.x4.shared.b16 {%0,%1,%2,%3}, [%4];"
                 : "=r"(r0), "=r"(r1), "=r"(r2), "=r"(r3) : "r"(a));
}
__device__ __forceinline__ void mma16816(float* d, const uint32_t* a,
                                         const uint32_t* b) {
    asm volatile(
        "mma.sync.aligned.m16n8k16.row.col.f32.bf16.bf16.f32 "
        "{%0,%1,%2,%3}, {%4,%5,%6,%7}, {%8,%9}, {%0,%1,%2,%3};"
        : "+f"(d[0]), "+f"(d[1]), "+f"(d[2]), "+f"(d[3])
        : "r"(a[0]), "r"(a[1]), "r"(a[2]), "r"(a[3]), "r"(b[0]), "r"(b[1]));
}

// ---------------- fp32 -> bf16 hi/lo split ----------------------------------
__device__ __forceinline__ void split_store4(float4 v,
                                             __nv_bfloat16* __restrict__ hi,
                                             __nv_bfloat16* __restrict__ lo) {
    __nv_bfloat16 h[4], l[4];
    float f[4] = {v.x, v.y, v.z, v.w};
    #pragma unroll
    for (int i = 0; i < 4; i++) {
        h[i] = __float2bfloat16(f[i]);
        l[i] = __float2bfloat16(f[i] - __bfloat162float(h[i]));
    }
    *(uint2*)hi = *(const uint2*)h;
    *(uint2*)lo = *(const uint2*)l;
}
__device__ __forceinline__ uint32_t pack_hi2(float a, float b) {
    __nv_bfloat16 h[2] = {__float2bfloat16(a), __float2bfloat16(b)};
    return *(const uint32_t*)h;
}
__device__ __forceinline__ uint32_t pack_lo2(float a, float b) {
    __nv_bfloat16 ha = __float2bfloat16(a), hb = __float2bfloat16(b);
    __nv_bfloat16 l[2] = {__float2bfloat16(a - __bfloat162float(ha)),
                          __float2bfloat16(b - __bfloat162float(hb))};
    return *(const uint32_t*)l;
}

// ---------------- block reductions ------------------------------------------
__device__ __forceinline__ float blk_sum256(float v) {
    __shared__ float red[8];
    __shared__ float tot;
    #pragma unroll
    for (int o = 16; o > 0; o >>= 1) v += __shfl_xor_sync(0xffffffffu, v, o);
    if ((threadIdx.x & 31) == 0) red[threadIdx.x >> 5] = v;
    __syncthreads();
    if (threadIdx.x == 0) {
        float s = 0.f;
        #pragma unroll
        for (int i = 0; i < 8; i++) s += red[i];
        tot = s;
    }
    __syncthreads();
    return tot;
}
__device__ __forceinline__ float blk_max256(float v) {
    __shared__ float red[8];
    __shared__ float tot;
    #pragma unroll
    for (int o = 16; o > 0; o >>= 1) v = fmaxf(v, __shfl_xor_sync(0xffffffffu, v, o));
    if ((threadIdx.x & 31) == 0) red[threadIdx.x >> 5] = v;
    __syncthreads();
    if (threadIdx.x == 0) {
        float s = red[0];
        #pragma unroll
        for (int i = 1; i < 8; i++) s = fmaxf(s, red[i]);
        tot = s;
    }
    __syncthreads();
    return tot;
}

// ---------------- K1: scale_shift = emb @ W_emb + b_emb ---------------------
__global__ void k_scale_shift(const float* __restrict__ emb,
                              const float* __restrict__ W,
                              const float* __restrict__ bias,
                              float* __restrict__ ss) {
    int c = blockIdx.x * 256 + threadIdx.x;
    int b = blockIdx.y;
    const float* e = emb + b * DIM_;
    float acc = bias[c];
    const float* wp = W + c;
    #pragma unroll 8
    for (int k = 0; k < DIM_; k++)
        acc = fmaf(e[k], wp[(long long)k * (2 * DIM_)], acc);
    ss[b * (2 * DIM_) + c] = acc;
}

// ---------------- K2: xn = RMSNorm(x)*g*(1+scale)+shift  -> hi/lo bf16 ------
__global__ void k_xnorm(const float* __restrict__ x,
                        const float* __restrict__ g,
                        const float* __restrict__ ss,
                        __nv_bfloat16* __restrict__ xh,
                        __nv_bfloat16* __restrict__ xl) {
    long long row = blockIdx.x;
    int b = (int)(row >> 11);
    const float4* xr = (const float4*)(x + row * DIM_);
    float4 v0 = xr[threadIdx.x];
    float4 v1 = xr[threadIdx.x + 256];
    float s = v0.x * v0.x + v0.y * v0.y + v0.z * v0.z + v0.w * v0.w
            + v1.x * v1.x + v1.y * v1.y + v1.z * v1.z + v1.w * v1.w;
    s = blk_sum256(s);
    float r = rsqrtf(s * (1.f / DIM_) + 1e-6f);
    const float* sc = ss + b * (2 * DIM_);
    const float* sh = sc + DIM_;
    int c0 = threadIdx.x * 4;
    int c1 = (threadIdx.x + 256) * 4;
    float4 o0, o1;
    o0.x = fmaf(v0.x * r * g[c0 + 0], 1.f + sc[c0 + 0], sh[c0 + 0]);
    o0.y = fmaf(v0.y * r * g[c0 + 1], 1.f + sc[c0 + 1], sh[c0 + 1]);
    o0.z = fmaf(v0.z * r * g[c0 + 2], 1.f + sc[c0 + 2], sh[c0 + 2]);
    o0.w = fmaf(v0.w * r * g[c0 + 3], 1.f + sc[c0 + 3], sh[c0 + 3]);
    o1.x = fmaf(v1.x * r * g[c1 + 0], 1.f + sc[c1 + 0], sh[c1 + 0]);
    o1.y = fmaf(v1.y * r * g[c1 + 1], 1.f + sc[c1 + 1], sh[c1 + 1]);
    o1.z = fmaf(v1.z * r * g[c1 + 2], 1.f + sc[c1 + 2], sh[c1 + 2]);
    o1.w = fmaf(v1.w * r * g[c1 + 3], 1.f + sc[c1 + 3], sh[c1 + 3]);
    long long base = row * DIM_;
    split_store4(o0, xh + base + c0, xl + base + c0);
    split_store4(o1, xh + base + c1, xl + base + c1);
}

// ---------------- K3: transpose + split weights  W[KR,NC] -> T[NC,KR] -------
__global__ void k_tsplit(const float* __restrict__ W, int KR, int NC,
                         __nv_bfloat16* __restrict__ Th,
                         __nv_bfloat16* __restrict__ Tl) {
    __shared__ float t[32][33];
    int c0 = blockIdx.x * 32;
    int r0 = blockIdx.y * 32;
    for (int i = threadIdx.y; i < 32; i += 8)
        t[i][threadIdx.x] = W[(long long)(r0 + i) * NC + c0 + threadIdx.x];
    __syncthreads();
    for (int i = threadIdx.y; i < 32; i += 8) {
        float v = t[threadIdx.x][i];
        long long o = (long long)(c0 + i) * KR + r0 + threadIdx.x;
        __nv_bfloat16 h = __float2bfloat16(v);
        Th[o] = h;
        Tl[o] = __float2bfloat16(v - __bfloat162float(h));
    }
}

// ---------------- K5: per-head q/k RMSNorm + split --------------------------
__global__ void k_qknorm_split(const float* __restrict__ qkv,
                               const float* __restrict__ gq,
                               const float* __restrict__ gk,
                               __nv_bfloat16* __restrict__ qh,
                               __nv_bfloat16* __restrict__ ql) {
    int row = blockIdx.x;
    int h = threadIdx.x >> 5;
    int lane = threadIdx.x & 31;
    const float* q = qkv + (long long)row * QKVC_ + h * DH_;
    const float* k = q + DIM_;
    long long qo = (long long)row * (2 * DIM_) + h * DH_ + lane * 4;
    {
        float4 v = *(const float4*)(q + lane * 4);
        float s = v.x * v.x + v.y * v.y + v.z * v.z + v.w * v.w;
        #pragma unroll
        for (int o = 16; o > 0; o >>= 1) s += __shfl_xor_sync(0xffffffffu, s, o);
        float r = rsqrtf(s * (1.f / DH_) + 1e-6f);
        v.x *= r * gq[lane * 4 + 0]; v.y *= r * gq[lane * 4 + 1];
        v.z *= r * gq[lane * 4 + 2]; v.w *= r * gq[lane * 4 + 3];
        split_store4(v, qh + qo, ql + qo);
    }
    {
        float4 v = *(const float4*)(k + lane * 4);
        float s = v.x * v.x + v.y * v.y + v.z * v.z + v.w * v.w;
        #pragma unroll
        for (int o = 16; o > 0; o >>= 1) s += __shfl_xor_sync(0xffffffffu, s, o);
        float r = rsqrtf(s * (1.f / DH_) + 1e-6f);
        v.x *= r * gk[lane * 4 + 0]; v.y *= r * gk[lane * 4 + 1];
        v.z *= r * gk[lane * 4 + 2]; v.w *= r * gk[lane * 4 + 3];
        split_store4(v, qh + qo + DIM_, ql + qo + DIM_);
    }
}

// ---------------- K5b: v -> vT per head, split ------------------------------
__global__ void k_vsplit(const float* __restrict__ qkv,
                         __nv_bfloat16* __restrict__ vh,
                         __nv_bfloat16* __restrict__ vl) {
    __shared__ float t[32][33];
    int z = blockIdx.z, b = z >> 4, h = z & 15;
    int s0 = blockIdx.x * 32, d0 = blockIdx.y * 32;
    const float* src = qkv + (long long)b * N_ * QKVC_ + 2 * DIM_ + h * DH_;
    for (int i = threadIdx.y; i < 32; i += 8)
        t[i][threadIdx.x] = src[(long long)(s0 + i) * QKVC_ + d0 + threadIdx.x];
    __syncthreads();
    long long ob = (long long)z * DH_ * N_;
    for (int i = threadIdx.y; i < 32; i += 8) {
        float v = t[threadIdx.x][i];
        long long o = ob + (long long)(d0 + i) * N_ + s0 + threadIdx.x;
        __nv_bfloat16 hh = __float2bfloat16(v);
        vh[o] = hh;
        vl[o] = __float2bfloat16(v - __bfloat162float(hh));
    }
}

// ---------------- K7: softmax rows -> attn hi/lo bf16 -----------------------
__global__ void k_softmax_split(const float* __restrict__ logits,
                                __nv_bfloat16* __restrict__ ah,
                                __nv_bfloat16* __restrict__ al) {
    long long row = blockIdx.x;
    const float4* p = (const float4*)(logits + row * (long long)N_);
    float4 v0 = p[threadIdx.x];
    float4 v1 = p[threadIdx.x + 256];
    float mx = fmaxf(fmaxf(fmaxf(v0.x, v0.y), fmaxf(v0.z, v0.w)),
                     fmaxf(fmaxf(v1.x, v1.y), fmaxf(v1.z, v1.w)));
    mx = blk_max256(mx);
    v0.x = __expf(v0.x - mx); v0.y = __expf(v0.y - mx);
    v0.z = __expf(v0.z - mx); v0.w = __expf(v0.w - mx);
    v1.x = __expf(v1.x - mx); v1.y = __expf(v1.y - mx);
    v1.z = __expf(v1.z - mx); v1.w = __expf(v1.w - mx);
    float s = v0.x + v0.y + v0.z + v0.w + v1.x + v1.y + v1.z + v1.w;
    s = blk_sum256(s);
    float inv = 1.f / s;
    v0.x *= inv; v0.y *= inv; v0.z *= inv; v0.w *= inv;
    v1.x *= inv; v1.y *= inv; v1.z *= inv; v1.w *= inv;
    long long base = row * (long long)N_;
    split_store4(v0, ah + base + threadIdx.x * 4, al + base + threadIdx.x * 4);
    split_store4(v1, ah + base + (threadIdx.x + 256) * 4,
                     al + base + (threadIdx.x + 256) * 4);
}

// ---------------------------------------------------------------------------
// mma.sync bf16x3 GEMM:  C = alpha * (Ahi+Alo)(Bhi+Blo)^T  (+ Cadd)
//   Block 128x128, 8 warps (warp tile 64x32), K-chunk 64, 3-stage cp.async,
//   144B-padded rows (conflict-free ldmatrix), term-grouped MMA issue,
//   load-ahead-of-compute pipeline. Optional bf16 hi/lo split-out (Oh/Ol).
// ---------------------------------------------------------------------------
#define CHUNK  64
#define ROWB   144
#define TILEB  (128 * ROWB)          // 18432 B
#define STAGEB (4 * TILEB)           // 73728 B
#define NSTAGE 3
#define GEMM_SMEM (NSTAGE * STAGEB)  // 221184 B

__global__ void __launch_bounds__(256, 1)
gemm_bf16x3(const __nv_bfloat16* __restrict__ Ahi, const __nv_bfloat16* __restrict__ Alo,
            int lda,
            const __nv_bfloat16* __restrict__ Bhi, const __nv_bfloat16* __restrict__ Blo,
            int ldb,
            const float* __restrict__ Cadd, float* __restrict__ C,
            __nv_bfloat16* __restrict__ Oh, __nv_bfloat16* __restrict__ Ol,
            int ldc, int K,
            long long sAb, long long sAh, long long sBb, long long sBh,
            long long sCb, long long sCh, int H, float alpha) {
    extern __shared__ char smem[];
    uint32_t sb = smem_u32(smem);
    int tid = threadIdx.x;
    int wid = tid >> 5, lane = tid & 31;
    int warp_m = wid >> 2;     // 0..1  -> 64 rows each
    int warp_n = wid & 3;      // 0..3  -> 32 cols each

    int z = blockIdx.z;
    int bb = z / H, hh = z - bb * H;
    long long aoff = bb * sAb + hh * sAh;
    long long boff = bb * sBb + hh * sBh;
    long long coff = bb * sCb + hh * sCh;
    Ahi += aoff; Alo += aoff;
    Bhi += boff; Blo += boff;
    C += coff;
    if (Cadd) Cadd += coff;
    if (Oh) { Oh += coff; Ol += coff; }

    int row0 = blockIdx.y * 128;
    int col0 = blockIdx.x * 128;

    float acc[4][4][4];
    #pragma unroll
    for (int i = 0; i < 4; i++)
        #pragma unroll
        for (int j = 0; j < 4; j++)
            #pragma unroll
            for (int r = 0; r < 4; r++) acc[i][j][r] = 0.f;

    int NC = K / CHUNK;

    auto load_stage = [&](int slot, int k0) {
        uint32_t base = sb + slot * STAGEB;
        #pragma unroll
        for (int t = 0; t < 4; t++) {
            const __nv_bfloat16* p = (t == 0) ? Ahi : (t == 1) ? Alo
                                   : (t == 2) ? Bhi : Blo;
            int r0g = (t < 2) ? row0 : col0;
            int ld  = (t < 2) ? lda : ldb;
            #pragma unroll
            for (int j = 0; j < 4; j++) {
                int id  = tid + j * 256;      // 0..1023
                int rid = id >> 3;            // row 0..127
                int seg = id & 7;             // 16B segment
                cp16(base + (uint32_t)t * TILEB + (uint32_t)rid * ROWB + seg * 16,
                     p + (long long)(r0g + rid) * ld + k0 + seg * 8);
            }
        }
        cp_commit();
    };

    load_stage(0, 0);
    load_stage(1, CHUNK);

    int lr = lane & 15;                 // ldmatrix row within 16
    uint32_t lc = ((lane >> 4) << 4);   // 0 / 16 bytes (k8 half)

    for (int i = 0; i < NC; i++) {
        if (i < NC - 1) cp_wait<1>();
        else            cp_wait<0>();
        __syncthreads();
        if (i + 2 < NC) load_stage((i + 2) % NSTAGE, (i + 2) * CHUNK);

        int slot = i % NSTAGE;
        uint32_t abase = sb + slot * STAGEB + (uint32_t)(warp_m * 64 + lr) * ROWB + lc;
        uint32_t bbase = sb + slot * STAGEB + 2 * TILEB
                       + (uint32_t)(warp_n * 32 + lr) * ROWB + lc;

        #pragma unroll
        for (int s = 0; s < 4; s++) {
            uint32_t koff = s * 32;        // 16 bf16 per k-step
            uint32_t Ah[4][4], Al[4][4], Bh[4][2], Bl[4][2];
            #pragma unroll
            for (int mi = 0; mi < 4; mi++) {
                uint32_t a = abase + (uint32_t)(mi * 16) * ROWB + koff;
                ldsm4(Ah[mi][0], Ah[mi][1], Ah[mi][2], Ah[mi][3], a);
                ldsm4(Al[mi][0], Al[mi][1], Al[mi][2], Al[mi][3], a + TILEB);
            }
            #pragma unroll
            for (int np = 0; np < 2; np++) {
                uint32_t a = bbase + (uint32_t)(np * 16) * ROWB + koff;
                uint32_t r0, r1, r2, r3;
                ldsm4(r0, r1, r2, r3, a);
                Bh[2 * np][0] = r0; Bh[2 * np][1] = r2;
                Bh[2 * np + 1][0] = r1; Bh[2 * np + 1][1] = r3;
                ldsm4(r0, r1, r2, r3, a + TILEB);
                Bl[2 * np][0] = r0; Bl[2 * np][1] = r2;
                Bl[2 * np + 1][0] = r1; Bl[2 * np + 1][1] = r3;
            }
            // term-grouped: 16 independent MMAs per term, no dependent chains
            #pragma unroll
            for (int mi = 0; mi < 4; mi++)
                #pragma unroll
                for (int ni = 0; ni < 4; ni++)
                    mma16816(acc[mi][ni], Ah[mi], Bh[ni]);
            #pragma unroll
            for (int mi = 0; mi < 4; mi++)
                #pragma unroll
                for (int ni = 0; ni < 4; ni++)
                    mma16816(acc[mi][ni], Ah[mi], Bl[ni]);
            #pragma unroll
            for (int mi = 0; mi < 4; mi++)
                #pragma unroll
                for (int ni = 0; ni < 4; ni++)
                    mma16816(acc[mi][ni], Al[mi], Bh[ni]);
        }
    }

    // ---- epilogue ------------------------------------------------------
    bool addc = (Cadd != nullptr);
    bool split = (Oh != nullptr);
    int mrow = row0 + warp_m * 64 + (lane >> 2);
    int ccol = col0 + warp_n * 32 + (lane & 3) * 2;
    #pragma unroll
    for (int mi = 0; mi < 4; mi++) {
        #pragma unroll
        for (int ni = 0; ni < 4; ni++) {
            long long o0 = (long long)(mrow + mi * 16) * ldc + ccol + ni * 8;
            long long o1 = o0 + 8LL * ldc;
            float2 v0 = make_float2(acc[mi][ni][0] * alpha, acc[mi][ni][1] * alpha);
            float2 v1 = make_float2(acc[mi][ni][2] * alpha, acc[mi][ni][3] * alpha);
            if (addc) {
                float2 c0 = *(const float2*)(Cadd + o0);
                float2 c1 = *(const float2*)(Cadd + o1);
                v0.x += c0.x; v0.y += c0.y;
                v1.x += c1.x; v1.y += c1.y;
            }
            *(float2*)(C + o0) = v0;
            *(float2*)(C + o1) = v1;
            if (split) {
                *(uint32_t*)(Oh + o0) = pack_hi2(v0.x, v0.y);
                *(uint32_t*)(Ol + o0) = pack_lo2(v0.x, v0.y);
                *(uint32_t*)(Oh + o1) = pack_hi2(v1.x, v1.y);
                *(uint32_t*)(Ol + o1) = pack_lo2(v1.x, v1.y);
            }
        }
    }
}

// ---------------------------------------------------------------------------
extern "C" void kernel_launch(void* const* d_in, const int* in_sizes, int n_in,
                              void* d_out, int out_size) {
    const float* x      = (const float*)d_in[0];
    const float* emb    = (const float*)d_in[1];
    const float* W_emb  = (const float*)d_in[2];
    const float* b_emb  = (const float*)d_in[3];
    const float* g_norm = (const float*)d_in[4];
    const float* W_qkv  = (const float*)d_in[5];
    const float* g_q    = (const float*)d_in[6];
    const float* g_k    = (const float*)d_in[7];
    const float* W_out  = (const float*)d_in[8];
    float* out = (float*)d_out;
    (void)in_sizes; (void)n_in; (void)out_size;

    float *ss, *qkv, *logits, *otok;
    __nv_bfloat16 *xnh, *xnl, *wqTh, *wqTl, *woTh, *woTl;
    __nv_bfloat16 *qkh, *qkl, *vTh, *vTl, *ah, *al, *oh, *ol;
    cudaGetSymbolAddress((void**)&ss,     g_ss);
    cudaGetSymbolAddress((void**)&xnh,    g_xnh);
    cudaGetSymbolAddress((void**)&xnl,    g_xnl);
    cudaGetSymbolAddress((void**)&wqTh,   g_wqTh);
    cudaGetSymbolAddress((void**)&wqTl,   g_wqTl);
    cudaGetSymbolAddress((void**)&woTh,   g_woTh);
    cudaGetSymbolAddress((void**)&woTl,   g_woTl);
    cudaGetSymbolAddress((void**)&qkv,    g_qkv);
    cudaGetSymbolAddress((void**)&qkh,    g_qkh);
    cudaGetSymbolAddress((void**)&qkl,    g_qkl);
    cudaGetSymbolAddress((void**)&vTh,    g_vTh);
    cudaGetSymbolAddress((void**)&vTl,    g_vTl);
    cudaGetSymbolAddress((void**)&logits, g_logits);
    cudaGetSymbolAddress((void**)&ah,     g_ah);
    cudaGetSymbolAddress((void**)&al,     g_al);
    cudaGetSymbolAddress((void**)&otok,   g_otok);
    cudaGetSymbolAddress((void**)&oh,     g_oh);
    cudaGetSymbolAddress((void**)&ol,     g_ol);

    cudaFuncSetAttribute(gemm_bf16x3,
                         cudaFuncAttributeMaxDynamicSharedMemorySize, GEMM_SMEM);

    const float att_scale = 0.08838834764831845f;   // 1/sqrt(128)

    // 1) scale/shift
    k_scale_shift<<<dim3((2 * DIM_) / 256, B_), 256>>>(emb, W_emb, b_emb, ss);

    // 2) AdaLN RMSNorm -> xn hi/lo
    k_xnorm<<<TOK_, 256>>>(x, g_norm, ss, xnh, xnl);

    // 3) transpose + split W_qkv
    k_tsplit<<<dim3(QKVC_ / 32, DIM_ / 32), dim3(32, 8)>>>(W_qkv, DIM_, QKVC_, wqTh, wqTl);

    // 4) QKV GEMM: [8192,2048] x [2048,6144] -> qkv fp32   (4th launch: profiled)
    gemm_bf16x3<<<dim3(QKVC_ / 128, TOK_ / 128, 1), 256, GEMM_SMEM>>>(
        xnh, xnl, DIM_, wqTh, wqTl, DIM_, nullptr, qkv, nullptr, nullptr, QKVC_,
        DIM_, 0, 0, 0, 0, 0, 0, 1, 1.0f);

    // 5) per-head q/k RMSNorm + split; v transpose + split
    k_qknorm_split<<<TOK_, 512>>>(qkv, g_q, g_k, qkh, qkl);
    k_vsplit<<<dim3(N_ / 32, DH_ / 32, BH_), dim3(32, 8)>>>(qkv, vTh, vTl);

    // 6) logits = q @ k^T * scale  (batched bh)
    gemm_bf16x3<<<dim3(N_ / 128, N_ / 128, BH_), 256, GEMM_SMEM>>>(
        qkh, qkl, 2 * DIM_, qkh + DIM_, qkl + DIM_, 2 * DIM_,
        nullptr, logits, nullptr, nullptr, N_,
        DH_,
        (long long)N_ * 2 * DIM_, DH_,
        (long long)N_ * 2 * DIM_, DH_,
        (long long)H_ * N_ * N_, (long long)N_ * N_,
        H_, att_scale);

    // 7) softmax -> attn hi/lo
    k_softmax_split<<<BH_ * N_, 256>>>(logits, ah, al);

    // 8) o = attn @ v  -> otok fp32 + fused hi/lo split
    gemm_bf16x3<<<dim3(1, N_ / 128, BH_), 256, GEMM_SMEM>>>(
        ah, al, N_, vTh, vTl, N_, nullptr, otok, oh, ol, DIM_,
        N_,
        (long long)H_ * N_ * N_, (long long)N_ * N_,
        (long long)H_ * DH_ * N_, (long long)DH_ * N_,
        (long long)N_ * DIM_, (long long)DH_,
        H_, 1.0f);

    // 9) transpose + split W_out
    k_tsplit<<<dim3(DIM_ / 32, DIM_ / 32), dim3(32, 8)>>>(W_out, DIM_, DIM_, woTh, woTl);

    // 10) out = o + o @ W_out
    gemm_bf16x3<<<dim3(DIM_ / 128, TOK_ / 128, 1), 256, GEMM_SMEM>>>(
        oh, ol, DIM_, woTh, woTl, DIM_, otok, out, nullptr, nullptr, DIM_,
        DIM_, 0, 0, 0, 0, 0, 0, 1, 1.0f);
}

// round 7
// speedup vs baseline: 2.1081x; 1.1623x over previous
#include <cuda_runtime.h>
#include <cuda_bf16.h>
#include <cstdint>

// ---------------------------------------------------------------------------
// AttentionBlock: b=4, n=2048, dim=2048, heads=16, d_head=128  (fp32 I/O)
// GEMMs: mma.sync.m16n8k16 bf16 with 3-term hi/lo split (fp32-accurate).
// R6: XOR-swizzled 64B rows (aligned cp.async), 3-stage, 2 CTAs/SM.
// ---------------------------------------------------------------------------

#define B_     4
#define N_     2048
#define DIM_   2048
#define H_     16
#define DH_    128
#define TOK_   (B_ * N_)          // 8192
#define QKVC_  (3 * DIM_)         // 6144
#define BH_    (B_ * H_)          // 64

// ---------------- scratch (__device__ globals) ------------------------------
__device__ float          g_ss[B_ * 2 * DIM_];
__device__ __nv_bfloat16  g_xnh[(long long)TOK_ * DIM_];
__device__ __nv_bfloat16  g_xnl[(long long)TOK_ * DIM_];
__device__ __nv_bfloat16  g_wqTh[(long long)QKVC_ * DIM_];
__device__ __nv_bfloat16  g_wqTl[(long long)QKVC_ * DIM_];
__device__ __nv_bfloat16  g_woTh[(long long)DIM_ * DIM_];
__device__ __nv_bfloat16  g_woTl[(long long)DIM_ * DIM_];
__device__ float          g_qkv[(long long)TOK_ * QKVC_];
__device__ __nv_bfloat16  g_qkh[(long long)TOK_ * 2 * DIM_];
__device__ __nv_bfloat16  g_qkl[(long long)TOK_ * 2 * DIM_];
__device__ __nv_bfloat16  g_vTh[(long long)BH_ * DH_ * N_];
__device__ __nv_bfloat16  g_vTl[(long long)BH_ * DH_ * N_];
__device__ float          g_logits[(long long)BH_ * N_ * N_];
__device__ __nv_bfloat16  g_ah[(long long)BH_ * N_ * N_];
__device__ __nv_bfloat16  g_al[(long long)BH_ * N_ * N_];
__device__ float          g_otok[(long long)TOK_ * DIM_];
__device__ __nv_bfloat16  g_oh[(long long)TOK_ * DIM_];
__device__ __nv_bfloat16  g_ol[(long long)TOK_ * DIM_];

// ---------------- PTX helpers ------------------------------------------------
__device__ __forceinline__ uint32_t smem_u32(const void* p) {
    uint32_t a;
    asm("{ .reg .u64 t; cvta.to.shared.u64 t, %1; cvt.u32.u64 %0, t; }"
        : "=r"(a) : "l"(p));
    return a;
}
__device__ __forceinline__ void cp16(uint32_t dst, const void* src) {
    asm volatile("cp.async.cg.shared.global [%0], [%1], 16;"
                 :: "r"(dst), "l"(__cvta_generic_to_global(src)));
}
__device__ __forceinline__ void cp_commit() {
    asm volatile("cp.async.commit_group;" ::: "memory");
}
template <int NN>
__device__ __forceinline__ void cp_wait() {
    asm volatile("cp.async.wait_group %0;" :: "n"(NN) : "memory");
}
__device__ __forceinline__ void ldsm4(uint32_t& r0, uint32_t& r1,
                                      uint32_t& r2, uint32_t& r3, uint32_t a) {
    asm volatile("ldmatrix.sync.aligned.m8n8.x4.shared.b16 {%0,%1,%2,%3}, [%4];"
                 : "=r"(r0), "=r"(r1), "=r"(r2), "=r"(r3) : "r"(a));
}
__device__ __forceinline__ void mma16816(float* d, const uint32_t* a,
                                         const uint32_t* b) {
    asm volatile(
        "mma.sync.aligned.m16n8k16.row.col.f32.bf16.bf16.f32 "
        "{%0,%1,%2,%3}, {%4,%5,%6,%7}, {%8,%9}, {%0,%1,%2,%3};"
        : "+f"(d[0]), "+f"(d[1]), "+f"(d[2]), "+f"(d[3])
        : "r"(a[0]), "r"(a[1]), "r"(a[2]), "r"(a[3]), "r"(b[0]), "r"(b[1]));
}

// ---------------- fp32 -> bf16 hi/lo split ----------------------------------
__device__ __forceinline__ void split_store4(float4 v,
                                             __nv_bfloat16* __restrict__ hi,
                                             __nv_bfloat16* __restrict__ lo) {
    __nv_bfloat16 h[4], l[4];
    float f[4] = {v.x, v.y, v.z, v.w};
    #pragma unroll
    for (int i = 0; i < 4; i++) {
        h[i] = __float2bfloat16(f[i]);
        l[i] = __float2bfloat16(f[i] - __bfloat162float(h[i]));
    }
    *(uint2*)hi = *(const uint2*)h;
    *(uint2*)lo = *(const uint2*)l;
}
__device__ __forceinline__ uint32_t pack_hi2(float a, float b) {
    __nv_bfloat16 h[2] = {__float2bfloat16(a), __float2bfloat16(b)};
    return *(const uint32_t*)h;
}
__device__ __forceinline__ uint32_t pack_lo2(float a, float b) {
    __nv_bfloat16 ha = __float2bfloat16(a), hb = __float2bfloat16(b);
    __nv_bfloat16 l[2] = {__float2bfloat16(a - __bfloat162float(ha)),
                          __float2bfloat16(b - __bfloat162float(hb))};
    return *(const uint32_t*)l;
}

// ---------------- block reductions ------------------------------------------
__device__ __forceinline__ float blk_sum256(float v) {
    __shared__ float red[8];
    __shared__ float tot;
    #pragma unroll
    for (int o = 16; o > 0; o >>= 1) v += __shfl_xor_sync(0xffffffffu, v, o);
    if ((threadIdx.x & 31) == 0) red[threadIdx.x >> 5] = v;
    __syncthreads();
    if (threadIdx.x == 0) {
        float s = 0.f;
        #pragma unroll
        for (int i = 0; i < 8; i++) s += red[i];
        tot = s;
    }
    __syncthreads();
    return tot;
}
__device__ __forceinline__ float blk_max256(float v) {
    __shared__ float red[8];
    __shared__ float tot;
    #pragma unroll
    for (int o = 16; o > 0; o >>= 1) v = fmaxf(v, __shfl_xor_sync(0xffffffffu, v, o));
    if ((threadIdx.x & 31) == 0) red[threadIdx.x >> 5] = v;
    __syncthreads();
    if (threadIdx.x == 0) {
        float s = red[0];
        #pragma unroll
        for (int i = 1; i < 8; i++) s = fmaxf(s, red[i]);
        tot = s;
    }
    __syncthreads();
    return tot;
}

// ---------------- K1: scale_shift = emb @ W_emb + b_emb ---------------------
__global__ void k_scale_shift(const float* __restrict__ emb,
                              const float* __restrict__ W,
                              const float* __restrict__ bias,
                              float* __restrict__ ss) {
    int c = blockIdx.x * 256 + threadIdx.x;
    int b = blockIdx.y;
    const float* e = emb + b * DIM_;
    float acc = bias[c];
    const float* wp = W + c;
    #pragma unroll 8
    for (int k = 0; k < DIM_; k++)
        acc = fmaf(e[k], wp[(long long)k * (2 * DIM_)], acc);
    ss[b * (2 * DIM_) + c] = acc;
}

// ---------------- K2: xn = RMSNorm(x)*g*(1+scale)+shift  -> hi/lo bf16 ------
__global__ void k_xnorm(const float* __restrict__ x,
                        const float* __restrict__ g,
                        const float* __restrict__ ss,
                        __nv_bfloat16* __restrict__ xh,
                        __nv_bfloat16* __restrict__ xl) {
    long long row = blockIdx.x;
    int b = (int)(row >> 11);
    const float4* xr = (const float4*)(x + row * DIM_);
    float4 v0 = xr[threadIdx.x];
    float4 v1 = xr[threadIdx.x + 256];
    float s = v0.x * v0.x + v0.y * v0.y + v0.z * v0.z + v0.w * v0.w
            + v1.x * v1.x + v1.y * v1.y + v1.z * v1.z + v1.w * v1.w;
    s = blk_sum256(s);
    float r = rsqrtf(s * (1.f / DIM_) + 1e-6f);
    const float* sc = ss + b * (2 * DIM_);
    const float* sh = sc + DIM_;
    int c0 = threadIdx.x * 4;
    int c1 = (threadIdx.x + 256) * 4;
    float4 o0, o1;
    o0.x = fmaf(v0.x * r * g[c0 + 0], 1.f + sc[c0 + 0], sh[c0 + 0]);
    o0.y = fmaf(v0.y * r * g[c0 + 1], 1.f + sc[c0 + 1], sh[c0 + 1]);
    o0.z = fmaf(v0.z * r * g[c0 + 2], 1.f + sc[c0 + 2], sh[c0 + 2]);
    o0.w = fmaf(v0.w * r * g[c0 + 3], 1.f + sc[c0 + 3], sh[c0 + 3]);
    o1.x = fmaf(v1.x * r * g[c1 + 0], 1.f + sc[c1 + 0], sh[c1 + 0]);
    o1.y = fmaf(v1.y * r * g[c1 + 1], 1.f + sc[c1 + 1], sh[c1 + 1]);
    o1.z = fmaf(v1.z * r * g[c1 + 2], 1.f + sc[c1 + 2], sh[c1 + 2]);
    o1.w = fmaf(v1.w * r * g[c1 + 3], 1.f + sc[c1 + 3], sh[c1 + 3]);
    long long base = row * DIM_;
    split_store4(o0, xh + base + c0, xl + base + c0);
    split_store4(o1, xh + base + c1, xl + base + c1);
}

// ---------------- K3: transpose + split weights  W[KR,NC] -> T[NC,KR] -------
__global__ void k_tsplit(const float* __restrict__ W, int KR, int NC,
                         __nv_bfloat16* __restrict__ Th,
                         __nv_bfloat16* __restrict__ Tl) {
    __shared__ float t[32][33];
    int c0 = blockIdx.x * 32;
    int r0 = blockIdx.y * 32;
    for (int i = threadIdx.y; i < 32; i += 8)
        t[i][threadIdx.x] = W[(long long)(r0 + i) * NC + c0 + threadIdx.x];
    __syncthreads();
    for (int i = threadIdx.y; i < 32; i += 8) {
        float v = t[threadIdx.x][i];
        long long o = (long long)(c0 + i) * KR + r0 + threadIdx.x;
        __nv_bfloat16 h = __float2bfloat16(v);
        Th[o] = h;
        Tl[o] = __float2bfloat16(v - __bfloat162float(h));
    }
}

// ---------------- K5: per-head q/k RMSNorm + split --------------------------
__global__ void k_qknorm_split(const float* __restrict__ qkv,
                               const float* __restrict__ gq,
                               const float* __restrict__ gk,
                               __nv_bfloat16* __restrict__ qh,
                               __nv_bfloat16* __restrict__ ql) {
    int row = blockIdx.x;
    int h = threadIdx.x >> 5;
    int lane = threadIdx.x & 31;
    const float* q = qkv + (long long)row * QKVC_ + h * DH_;
    const float* k = q + DIM_;
    long long qo = (long long)row * (2 * DIM_) + h * DH_ + lane * 4;
    {
        float4 v = *(const float4*)(q + lane * 4);
        float s = v.x * v.x + v.y * v.y + v.z * v.z + v.w * v.w;
        #pragma unroll
        for (int o = 16; o > 0; o >>= 1) s += __shfl_xor_sync(0xffffffffu, s, o);
        float r = rsqrtf(s * (1.f / DH_) + 1e-6f);
        v.x *= r * gq[lane * 4 + 0]; v.y *= r * gq[lane * 4 + 1];
        v.z *= r * gq[lane * 4 + 2]; v.w *= r * gq[lane * 4 + 3];
        split_store4(v, qh + qo, ql + qo);
    }
    {
        float4 v = *(const float4*)(k + lane * 4);
        float s = v.x * v.x + v.y * v.y + v.z * v.z + v.w * v.w;
        #pragma unroll
        for (int o = 16; o > 0; o >>= 1) s += __shfl_xor_sync(0xffffffffu, s, o);
        float r = rsqrtf(s * (1.f / DH_) + 1e-6f);
        v.x *= r * gk[lane * 4 + 0]; v.y *= r * gk[lane * 4 + 1];
        v.z *= r * gk[lane * 4 + 2]; v.w *= r * gk[lane * 4 + 3];
        split_store4(v, qh + qo + DIM_, ql + qo + DIM_);
    }
}

// ---------------- K5b: v -> vT per head, split ------------------------------
__global__ void k_vsplit(const float* __restrict__ qkv,
                         __nv_bfloat16* __restrict__ vh,
                         __nv_bfloat16* __restrict__ vl) {
    __shared__ float t[32][33];
    int z = blockIdx.z, b = z >> 4, h = z & 15;
    int s0 = blockIdx.x * 32, d0 = blockIdx.y * 32;
    const float* src = qkv + (long long)b * N_ * QKVC_ + 2 * DIM_ + h * DH_;
    for (int i = threadIdx.y; i < 32; i += 8)
        t[i][threadIdx.x] = src[(long long)(s0 + i) * QKVC_ + d0 + threadIdx.x];
    __syncthreads();
    long long ob = (long long)z * DH_ * N_;
    for (int i = threadIdx.y; i < 32; i += 8) {
        float v = t[threadIdx.x][i];
        long long o = ob + (long long)(d0 + i) * N_ + s0 + threadIdx.x;
        __nv_bfloat16 hh = __float2bfloat16(v);
        vh[o] = hh;
        vl[o] = __float2bfloat16(v - __bfloat162float(hh));
    }
}

// ---------------- K7: softmax rows -> attn hi/lo bf16 -----------------------
__global__ void k_softmax_split(const float* __restrict__ logits,
                                __nv_bfloat16* __restrict__ ah,
                                __nv_bfloat16* __restrict__ al) {
    long long row = blockIdx.x;
    const float4* p = (const float4*)(logits + row * (long long)N_);
    float4 v0 = p[threadIdx.x];
    float4 v1 = p[threadIdx.x + 256];
    float mx = fmaxf(fmaxf(fmaxf(v0.x, v0.y), fmaxf(v0.z, v0.w)),
                     fmaxf(fmaxf(v1.x, v1.y), fmaxf(v1.z, v1.w)));
    mx = blk_max256(mx);
    v0.x = __expf(v0.x - mx); v0.y = __expf(v0.y - mx);
    v0.z = __expf(v0.z - mx); v0.w = __expf(v0.w - mx);
    v1.x = __expf(v1.x - mx); v1.y = __expf(v1.y - mx);
    v1.z = __expf(v1.z - mx); v1.w = __expf(v1.w - mx);
    float s = v0.x + v0.y + v0.z + v0.w + v1.x + v1.y + v1.z + v1.w;
    s = blk_sum256(s);
    float inv = 1.f / s;
    v0.x *= inv; v0.y *= inv; v0.z *= inv; v0.w *= inv;
    v1.x *= inv; v1.y *= inv; v1.z *= inv; v1.w *= inv;
    long long base = row * (long long)N_;
    split_store4(v0, ah + base + threadIdx.x * 4, al + base + threadIdx.x * 4);
    split_store4(v1, ah + base + (threadIdx.x + 256) * 4,
                     al + base + (threadIdx.x + 256) * 4);
}

// ---------------------------------------------------------------------------
// mma.sync bf16x3 GEMM:  C = alpha * (Ahi+Alo)(Bhi+Blo)^T  (+ Cadd)
//   Block 128x128, 8 warps (warp tile 64x32), K-chunk 32, 3-stage cp.async,
//   XOR-swizzled 64B rows (chunk' = chunk ^ ((row>>1)&3): aligned + conflict-
//   free), term-sequenced fragments (low regs), 2 CTAs/SM.
// ---------------------------------------------------------------------------
#define CHUNK  32
#define ROWB   64
#define TILEB  (128 * ROWB)          // 8192 B
#define STAGEB (4 * TILEB)           // 32768 B
#define NSTAGE 3
#define GEMM_SMEM (NSTAGE * STAGEB)  // 98304 B

__global__ void __launch_bounds__(256, 2)
gemm_bf16x3(const __nv_bfloat16* __restrict__ Ahi, const __nv_bfloat16* __restrict__ Alo,
            int lda,
            const __nv_bfloat16* __restrict__ Bhi, const __nv_bfloat16* __restrict__ Blo,
            int ldb,
            const float* __restrict__ Cadd, float* __restrict__ C,
            __nv_bfloat16* __restrict__ Oh, __nv_bfloat16* __restrict__ Ol,
            int ldc, int K,
            long long sAb, long long sAh, long long sBb, long long sBh,
            long long sCb, long long sCh, int H, float alpha) {
    extern __shared__ char smem[];
    uint32_t sb = smem_u32(smem);
    int tid = threadIdx.x;
    int wid = tid >> 5, lane = tid & 31;
    int warp_m = wid >> 2;     // 0..1  -> 64 rows each
    int warp_n = wid & 3;      // 0..3  -> 32 cols each

    int z = blockIdx.z;
    int bb = z / H, hh = z - bb * H;
    long long aoff = bb * sAb + hh * sAh;
    long long boff = bb * sBb + hh * sBh;
    long long coff = bb * sCb + hh * sCh;
    Ahi += aoff; Alo += aoff;
    Bhi += boff; Blo += boff;
    C += coff;
    if (Cadd) Cadd += coff;
    if (Oh) { Oh += coff; Ol += coff; }

    int row0 = blockIdx.y * 128;
    int col0 = blockIdx.x * 128;

    float acc[4][4][4];
    #pragma unroll
    for (int i = 0; i < 4; i++)
        #pragma unroll
        for (int j = 0; j < 4; j++)
            #pragma unroll
            for (int r = 0; r < 4; r++) acc[i][j][r] = 0.f;

    int NC = K / CHUNK;

    // store: row rid, 16B chunk seg -> offset rid*64 + (seg ^ ((rid>>1)&3))*16
    auto load_stage = [&](int slot, int k0) {
        uint32_t base = sb + slot * STAGEB;
        #pragma unroll
        for (int t = 0; t < 4; t++) {
            const __nv_bfloat16* p = (t == 0) ? Ahi : (t == 1) ? Alo
                                   : (t == 2) ? Bhi : Blo;
            int r0g = (t < 2) ? row0 : col0;
            int ld  = (t < 2) ? lda : ldb;
            #pragma unroll
            for (int j = 0; j < 2; j++) {
                int id  = tid + j * 256;      // 0..511
                int rid = id >> 2;            // row 0..127
                int seg = id & 3;             // logical 16B chunk
                int sw  = seg ^ ((rid >> 1) & 3);
                cp16(base + (uint32_t)t * TILEB + (uint32_t)(rid * ROWB + sw * 16),
                     p + (long long)(r0g + rid) * ld + k0 + seg * 8);
            }
        }
        cp_commit();
    };

    load_stage(0, 0);
    load_stage(1, CHUNK);

    int lr  = lane & 15;                // ldmatrix row within 16
    int cx  = lane >> 4;                // logical chunk half (0/1)
    int swz = (lr >> 1) & 3;            // per-thread swizzle key

    for (int i = 0; i < NC; i++) {
        if (i < NC - 1) cp_wait<1>();
        else            cp_wait<0>();
        __syncthreads();
        if (i + 2 < NC) load_stage((i + 2) % NSTAGE, (i + 2) * CHUNK);

        int slot = i % NSTAGE;
        uint32_t abase = sb + slot * STAGEB + (uint32_t)((warp_m * 64 + lr) * ROWB);
        uint32_t bbase = sb + slot * STAGEB + 2 * TILEB
                       + (uint32_t)((warp_n * 32 + lr) * ROWB);

        #pragma unroll
        for (int s = 0; s < 2; s++) {
            uint32_t co = (uint32_t)(((s << 1) | cx) ^ swz) << 4;  // swizzled col
            uint32_t A1[4][4], A2[4][4], Bf[4][2];
            // Ah + Bh
            #pragma unroll
            for (int mi = 0; mi < 4; mi++)
                ldsm4(A1[mi][0], A1[mi][1], A1[mi][2], A1[mi][3],
                      abase + (uint32_t)(mi * 16 * ROWB) + co);
            #pragma unroll
            for (int np = 0; np < 2; np++) {
                uint32_t r0, r1, r2, r3;
                ldsm4(r0, r1, r2, r3, bbase + (uint32_t)(np * 16 * ROWB) + co);
                Bf[2 * np][0] = r0; Bf[2 * np][1] = r2;
                Bf[2 * np + 1][0] = r1; Bf[2 * np + 1][1] = r3;
            }
            // hi*hi
            #pragma unroll
            for (int mi = 0; mi < 4; mi++)
                #pragma unroll
                for (int ni = 0; ni < 4; ni++)
                    mma16816(acc[mi][ni], A1[mi], Bf[ni]);
            // Al, then lo*hi (A2 x Bh still in Bf)
            #pragma unroll
            for (int mi = 0; mi < 4; mi++)
                ldsm4(A2[mi][0], A2[mi][1], A2[mi][2], A2[mi][3],
                      abase + (uint32_t)(mi * 16 * ROWB) + co + TILEB);
            #pragma unroll
            for (int mi = 0; mi < 4; mi++)
                #pragma unroll
                for (int ni = 0; ni < 4; ni++)
                    mma16816(acc[mi][ni], A2[mi], Bf[ni]);
            // Bl overwrites Bf, then hi*lo (A1 x Bl)
            #pragma unroll
            for (int np = 0; np < 2; np++) {
                uint32_t r0, r1, r2, r3;
                ldsm4(r0, r1, r2, r3,
                      bbase + (uint32_t)(np * 16 * ROWB) + co + TILEB);
                Bf[2 * np][0] = r0; Bf[2 * np][1] = r2;
                Bf[2 * np + 1][0] = r1; Bf[2 * np + 1][1] = r3;
            }
            #pragma unroll
            for (int mi = 0; mi < 4; mi++)
                #pragma unroll
                for (int ni = 0; ni < 4; ni++)
                    mma16816(acc[mi][ni], A1[mi], Bf[ni]);
        }
    }

    // ---- epilogue ------------------------------------------------------
    bool addc = (Cadd != nullptr);
    bool split = (Oh != nullptr);
    int mrow = row0 + warp_m * 64 + (lane >> 2);
    int ccol = col0 + warp_n * 32 + (lane & 3) * 2;
    #pragma unroll
    for (int mi = 0; mi < 4; mi++) {
        #pragma unroll
        for (int ni = 0; ni < 4; ni++) {
            long long o0 = (long long)(mrow + mi * 16) * ldc + ccol + ni * 8;
            long long o1 = o0 + 8LL * ldc;
            float2 v0 = make_float2(acc[mi][ni][0] * alpha, acc[mi][ni][1] * alpha);
            float2 v1 = make_float2(acc[mi][ni][2] * alpha, acc[mi][ni][3] * alpha);
            if (addc) {
                float2 c0 = *(const float2*)(Cadd + o0);
                float2 c1 = *(const float2*)(Cadd + o1);
                v0.x += c0.x; v0.y += c0.y;
                v1.x += c1.x; v1.y += c1.y;
            }
            *(float2*)(C + o0) = v0;
            *(float2*)(C + o1) = v1;
            if (split) {
                *(uint32_t*)(Oh + o0) = pack_hi2(v0.x, v0.y);
                *(uint32_t*)(Ol + o0) = pack_lo2(v0.x, v0.y);
                *(uint32_t*)(Oh + o1) = pack_hi2(v1.x, v1.y);
                *(uint32_t*)(Ol + o1) = pack_lo2(v1.x, v1.y);
            }
        }
    }
}

// ---------------------------------------------------------------------------
extern "C" void kernel_launch(void* const* d_in, const int* in_sizes, int n_in,
                              void* d_out, int out_size) {
    const float* x      = (const float*)d_in[0];
    const float* emb    = (const float*)d_in[1];
    const float* W_emb  = (const float*)d_in[2];
    const float* b_emb  = (const float*)d_in[3];
    const float* g_norm = (const float*)d_in[4];
    const float* W_qkv  = (const float*)d_in[5];
    const float* g_q    = (const float*)d_in[6];
    const float* g_k    = (const float*)d_in[7];
    const float* W_out  = (const float*)d_in[8];
    float* out = (float*)d_out;
    (void)in_sizes; (void)n_in; (void)out_size;

    float *ss, *qkv, *logits, *otok;
    __nv_bfloat16 *xnh, *xnl, *wqTh, *wqTl, *woTh, *woTl;
    __nv_bfloat16 *qkh, *qkl, *vTh, *vTl, *ah, *al, *oh, *ol;
    cudaGetSymbolAddress((void**)&ss,     g_ss);
    cudaGetSymbolAddress((void**)&xnh,    g_xnh);
    cudaGetSymbolAddress((void**)&xnl,    g_xnl);
    cudaGetSymbolAddress((void**)&wqTh,   g_wqTh);
    cudaGetSymbolAddress((void**)&wqTl,   g_wqTl);
    cudaGetSymbolAddress((void**)&woTh,   g_woTh);
    cudaGetSymbolAddress((void**)&woTl,   g_woTl);
    cudaGetSymbolAddress((void**)&qkv,    g_qkv);
    cudaGetSymbolAddress((void**)&qkh,    g_qkh);
    cudaGetSymbolAddress((void**)&qkl,    g_qkl);
    cudaGetSymbolAddress((void**)&vTh,    g_vTh);
    cudaGetSymbolAddress((void**)&vTl,    g_vTl);
    cudaGetSymbolAddress((void**)&logits, g_logits);
    cudaGetSymbolAddress((void**)&ah,     g_ah);
    cudaGetSymbolAddress((void**)&al,     g_al);
    cudaGetSymbolAddress((void**)&otok,   g_otok);
    cudaGetSymbolAddress((void**)&oh,     g_oh);
    cudaGetSymbolAddress((void**)&ol,     g_ol);

    cudaFuncSetAttribute(gemm_bf16x3,
                         cudaFuncAttributeMaxDynamicSharedMemorySize, GEMM_SMEM);

    const float att_scale = 0.08838834764831845f;   // 1/sqrt(128)

    // 1) scale/shift
    k_scale_shift<<<dim3((2 * DIM_) / 256, B_), 256>>>(emb, W_emb, b_emb, ss);

    // 2) AdaLN RMSNorm -> xn hi/lo
    k_xnorm<<<TOK_, 256>>>(x, g_norm, ss, xnh, xnl);

    // 3) transpose + split W_qkv
    k_tsplit<<<dim3(QKVC_ / 32, DIM_ / 32), dim3(32, 8)>>>(W_qkv, DIM_, QKVC_, wqTh, wqTl);

    // 4) QKV GEMM: [8192,2048] x [2048,6144] -> qkv fp32   (4th launch: profiled)
    gemm_bf16x3<<<dim3(QKVC_ / 128, TOK_ / 128, 1), 256, GEMM_SMEM>>>(
        xnh, xnl, DIM_, wqTh, wqTl, DIM_, nullptr, qkv, nullptr, nullptr, QKVC_,
        DIM_, 0, 0, 0, 0, 0, 0, 1, 1.0f);

    // 5) per-head q/k RMSNorm + split; v transpose + split
    k_qknorm_split<<<TOK_, 512>>>(qkv, g_q, g_k, qkh, qkl);
    k_vsplit<<<dim3(N_ / 32, DH_ / 32, BH_), dim3(32, 8)>>>(qkv, vTh, vTl);

    // 6) logits = q @ k^T * scale  (batched bh)
    gemm_bf16x3<<<dim3(N_ / 128, N_ / 128, BH_), 256, GEMM_SMEM>>>(
        qkh, qkl, 2 * DIM_, qkh + DIM_, qkl + DIM_, 2 * DIM_,
        nullptr, logits, nullptr, nullptr, N_,
        DH_,
        (long long)N_ * 2 * DIM_, DH_,
        (long long)N_ * 2 * DIM_, DH_,
        (long long)H_ * N_ * N_, (long long)N_ * N_,
        H_, att_scale);

    // 7) softmax -> attn hi/lo
    k_softmax_split<<<BH_ * N_, 256>>>(logits, ah, al);

    // 8) o = attn @ v  -> otok fp32 + fused hi/lo split
    gemm_bf16x3<<<dim3(1, N_ / 128, BH_), 256, GEMM_SMEM>>>(
        ah, al, N_, vTh, vTl, N_, nullptr, otok, oh, ol, DIM_,
        N_,
        (long long)H_ * N_ * N_, (long long)N_ * N_,
        (long long)H_ * DH_ * N_, (long long)DH_ * N_,
        (long long)N_ * DIM_, (long long)DH_,
        H_, 1.0f);

    // 9) transpose + split W_out
    k_tsplit<<<dim3(DIM_ / 32, DIM_ / 32), dim3(32, 8)>>>(W_out, DIM_, DIM_, woTh, woTl);

    // 10) out = o + o @ W_out
    gemm_bf16x3<<<dim3(DIM_ / 128, TOK_ / 128, 1), 256, GEMM_SMEM>>>(
        oh, ol, DIM_, woTh, woTl, DIM_, otok, out, nullptr, nullptr, DIM_,
        DIM_, 0, 0, 0, 0, 0, 0, 1, 1.0f);
}

// round 8
// speedup vs baseline: 2.1111x; 1.0014x over previous
#include <cuda_runtime.h>
#include <cuda_bf16.h>
#include <cstdint>

// ---------------------------------------------------------------------------
// AttentionBlock: b=4, n=2048, dim=2048, heads=16, d_head=128  (fp32 I/O)
// GEMMs: mma.sync.m16n8k16 bf16 with 3-term hi/lo split (fp32-accurate).
// R6: XOR-swizzled 64B rows (aligned cp.async), 3-stage, 2 CTAs/SM.
// ---------------------------------------------------------------------------

#define B_     4
#define N_     2048
#define DIM_   2048
#define H_     16
#define DH_    128
#define TOK_   (B_ * N_)          // 8192
#define QKVC_  (3 * DIM_)         // 6144
#define BH_    (B_ * H_)          // 64

// ---------------- scratch (__device__ globals) ------------------------------
__device__ float          g_ss[B_ * 2 * DIM_];
__device__ __nv_bfloat16  g_xnh[(long long)TOK_ * DIM_];
__device__ __nv_bfloat16  g_xnl[(long long)TOK_ * DIM_];
__device__ __nv_bfloat16  g_wqTh[(long long)QKVC_ * DIM_];
__device__ __nv_bfloat16  g_wqTl[(long long)QKVC_ * DIM_];
__device__ __nv_bfloat16  g_woTh[(long long)DIM_ * DIM_];
__device__ __nv_bfloat16  g_woTl[(long long)DIM_ * DIM_];
__device__ float          g_qkv[(long long)TOK_ * QKVC_];
__device__ __nv_bfloat16  g_qkh[(long long)TOK_ * 2 * DIM_];
__device__ __nv_bfloat16  g_qkl[(long long)TOK_ * 2 * DIM_];
__device__ __nv_bfloat16  g_vTh[(long long)BH_ * DH_ * N_];
__device__ __nv_bfloat16  g_vTl[(long long)BH_ * DH_ * N_];
__device__ float          g_logits[(long long)BH_ * N_ * N_];
__device__ __nv_bfloat16  g_ah[(long long)BH_ * N_ * N_];
__device__ __nv_bfloat16  g_al[(long long)BH_ * N_ * N_];
__device__ float          g_otok[(long long)TOK_ * DIM_];
__device__ __nv_bfloat16  g_oh[(long long)TOK_ * DIM_];
__device__ __nv_bfloat16  g_ol[(long long)TOK_ * DIM_];

// ---------------- PTX helpers ------------------------------------------------
__device__ __forceinline__ uint32_t smem_u32(const void* p) {
    uint32_t a;
    asm("{ .reg .u64 t; cvta.to.shared.u64 t, %1; cvt.u32.u64 %0, t; }"
        : "=r"(a) : "l"(p));
    return a;
}
__device__ __forceinline__ void cp16(uint32_t dst, const void* src) {
    asm volatile("cp.async.cg.shared.global [%0], [%1], 16;"
                 :: "r"(dst), "l"(__cvta_generic_to_global(src)));
}
__device__ __forceinline__ void cp_commit() {
    asm volatile("cp.async.commit_group;" ::: "memory");
}
template <int NN>
__device__ __forceinline__ void cp_wait() {
    asm volatile("cp.async.wait_group %0;" :: "n"(NN) : "memory");
}
__device__ __forceinline__ void ldsm4(uint32_t& r0, uint32_t& r1,
                                      uint32_t& r2, uint32_t& r3, uint32_t a) {
    asm volatile("ldmatrix.sync.aligned.m8n8.x4.shared.b16 {%0,%1,%2,%3}, [%4];"
                 : "=r"(r0), "=r"(r1), "=r"(r2), "=r"(r3) : "r"(a));
}
__device__ __forceinline__ void mma16816(float* d, const uint32_t* a,
                                         const uint32_t* b) {
    asm volatile(
        "mma.sync.aligned.m16n8k16.row.col.f32.bf16.bf16.f32 "
        "{%0,%1,%2,%3}, {%4,%5,%6,%7}, {%8,%9}, {%0,%1,%2,%3};"
        : "+f"(d[0]), "+f"(d[1]), "+f"(d[2]), "+f"(d[3])
        : "r"(a[0]), "r"(a[1]), "r"(a[2]), "r"(a[3]), "r"(b[0]), "r"(b[1]));
}

// ---------------- fp32 -> bf16 hi/lo split ----------------------------------
__device__ __forceinline__ void split_store4(float4 v,
                                             __nv_bfloat16* __restrict__ hi,
                                             __nv_bfloat16* __restrict__ lo) {
    __nv_bfloat16 h[4], l[4];
    float f[4] = {v.x, v.y, v.z, v.w};
    #pragma unroll
    for (int i = 0; i < 4; i++) {
        h[i] = __float2bfloat16(f[i]);
        l[i] = __float2bfloat16(f[i] - __bfloat162float(h[i]));
    }
    *(uint2*)hi = *(const uint2*)h;
    *(uint2*)lo = *(const uint2*)l;
}
__device__ __forceinline__ uint32_t pack_hi2(float a, float b) {
    __nv_bfloat16 h[2] = {__float2bfloat16(a), __float2bfloat16(b)};
    return *(const uint32_t*)h;
}
__device__ __forceinline__ uint32_t pack_lo2(float a, float b) {
    __nv_bfloat16 ha = __float2bfloat16(a), hb = __float2bfloat16(b);
    __nv_bfloat16 l[2] = {__float2bfloat16(a - __bfloat162float(ha)),
                          __float2bfloat16(b - __bfloat162float(hb))};
    return *(const uint32_t*)l;
}

// ---------------- block reductions ------------------------------------------
__device__ __forceinline__ float blk_sum256(float v) {
    __shared__ float red[8];
    __shared__ float tot;
    #pragma unroll
    for (int o = 16; o > 0; o >>= 1) v += __shfl_xor_sync(0xffffffffu, v, o);
    if ((threadIdx.x & 31) == 0) red[threadIdx.x >> 5] = v;
    __syncthreads();
    if (threadIdx.x == 0) {
        float s = 0.f;
        #pragma unroll
        for (int i = 0; i < 8; i++) s += red[i];
        tot = s;
    }
    __syncthreads();
    return tot;
}
__device__ __forceinline__ float blk_max256(float v) {
    __shared__ float red[8];
    __shared__ float tot;
    #pragma unroll
    for (int o = 16; o > 0; o >>= 1) v = fmaxf(v, __shfl_xor_sync(0xffffffffu, v, o));
    if ((threadIdx.x & 31) == 0) red[threadIdx.x >> 5] = v;
    __syncthreads();
    if (threadIdx.x == 0) {
        float s = red[0];
        #pragma unroll
        for (int i = 1; i < 8; i++) s = fmaxf(s, red[i]);
        tot = s;
    }
    __syncthreads();
    return tot;
}

// ---------------- K1: scale_shift = emb @ W_emb + b_emb ---------------------
__global__ void k_scale_shift(const float* __restrict__ emb,
                              const float* __restrict__ W,
                              const float* __restrict__ bias,
                              float* __restrict__ ss) {
    int c = blockIdx.x * 256 + threadIdx.x;
    int b = blockIdx.y;
    const float* e = emb + b * DIM_;
    float acc = bias[c];
    const float* wp = W + c;
    #pragma unroll 8
    for (int k = 0; k < DIM_; k++)
        acc = fmaf(e[k], wp[(long long)k * (2 * DIM_)], acc);
    ss[b * (2 * DIM_) + c] = acc;
}

// ---------------- K2: xn = RMSNorm(x)*g*(1+scale)+shift  -> hi/lo bf16 ------
__global__ void k_xnorm(const float* __restrict__ x,
                        const float* __restrict__ g,
                        const float* __restrict__ ss,
                        __nv_bfloat16* __restrict__ xh,
                        __nv_bfloat16* __restrict__ xl) {
    long long row = blockIdx.x;
    int b = (int)(row >> 11);
    const float4* xr = (const float4*)(x + row * DIM_);
    float4 v0 = xr[threadIdx.x];
    float4 v1 = xr[threadIdx.x + 256];
    float s = v0.x * v0.x + v0.y * v0.y + v0.z * v0.z + v0.w * v0.w
            + v1.x * v1.x + v1.y * v1.y + v1.z * v1.z + v1.w * v1.w;
    s = blk_sum256(s);
    float r = rsqrtf(s * (1.f / DIM_) + 1e-6f);
    const float* sc = ss + b * (2 * DIM_);
    const float* sh = sc + DIM_;
    int c0 = threadIdx.x * 4;
    int c1 = (threadIdx.x + 256) * 4;
    float4 o0, o1;
    o0.x = fmaf(v0.x * r * g[c0 + 0], 1.f + sc[c0 + 0], sh[c0 + 0]);
    o0.y = fmaf(v0.y * r * g[c0 + 1], 1.f + sc[c0 + 1], sh[c0 + 1]);
    o0.z = fmaf(v0.z * r * g[c0 + 2], 1.f + sc[c0 + 2], sh[c0 + 2]);
    o0.w = fmaf(v0.w * r * g[c0 + 3], 1.f + sc[c0 + 3], sh[c0 + 3]);
    o1.x = fmaf(v1.x * r * g[c1 + 0], 1.f + sc[c1 + 0], sh[c1 + 0]);
    o1.y = fmaf(v1.y * r * g[c1 + 1], 1.f + sc[c1 + 1], sh[c1 + 1]);
    o1.z = fmaf(v1.z * r * g[c1 + 2], 1.f + sc[c1 + 2], sh[c1 + 2]);
    o1.w = fmaf(v1.w * r * g[c1 + 3], 1.f + sc[c1 + 3], sh[c1 + 3]);
    long long base = row * DIM_;
    split_store4(o0, xh + base + c0, xl + base + c0);
    split_store4(o1, xh + base + c1, xl + base + c1);
}

// ---------------- K3: transpose + split weights  W[KR,NC] -> T[NC,KR] -------
__global__ void k_tsplit(const float* __restrict__ W, int KR, int NC,
                         __nv_bfloat16* __restrict__ Th,
                         __nv_bfloat16* __restrict__ Tl) {
    __shared__ float t[32][33];
    int c0 = blockIdx.x * 32;
    int r0 = blockIdx.y * 32;
    for (int i = threadIdx.y; i < 32; i += 8)
        t[i][threadIdx.x] = W[(long long)(r0 + i) * NC + c0 + threadIdx.x];
    __syncthreads();
    for (int i = threadIdx.y; i < 32; i += 8) {
        float v = t[threadIdx.x][i];
        long long o = (long long)(c0 + i) * KR + r0 + threadIdx.x;
        __nv_bfloat16 h = __float2bfloat16(v);
        Th[o] = h;
        Tl[o] = __float2bfloat16(v - __bfloat162float(h));
    }
}

// ---------------- K5: per-head q/k RMSNorm + split --------------------------
__global__ void k_qknorm_split(const float* __restrict__ qkv,
                               const float* __restrict__ gq,
                               const float* __restrict__ gk,
                               __nv_bfloat16* __restrict__ qh,
                               __nv_bfloat16* __restrict__ ql) {
    int row = blockIdx.x;
    int h = threadIdx.x >> 5;
    int lane = threadIdx.x & 31;
    const float* q = qkv + (long long)row * QKVC_ + h * DH_;
    const float* k = q + DIM_;
    long long qo = (long long)row * (2 * DIM_) + h * DH_ + lane * 4;
    {
        float4 v = *(const float4*)(q + lane * 4);
        float s = v.x * v.x + v.y * v.y + v.z * v.z + v.w * v.w;
        #pragma unroll
        for (int o = 16; o > 0; o >>= 1) s += __shfl_xor_sync(0xffffffffu, s, o);
        float r = rsqrtf(s * (1.f / DH_) + 1e-6f);
        v.x *= r * gq[lane * 4 + 0]; v.y *= r * gq[lane * 4 + 1];
        v.z *= r * gq[lane * 4 + 2]; v.w *= r * gq[lane * 4 + 3];
        split_store4(v, qh + qo, ql + qo);
    }
    {
        float4 v = *(const float4*)(k + lane * 4);
        float s = v.x * v.x + v.y * v.y + v.z * v.z + v.w * v.w;
        #pragma unroll
        for (int o = 16; o > 0; o >>= 1) s += __shfl_xor_sync(0xffffffffu, s, o);
        float r = rsqrtf(s * (1.f / DH_) + 1e-6f);
        v.x *= r * gk[lane * 4 + 0]; v.y *= r * gk[lane * 4 + 1];
        v.z *= r * gk[lane * 4 + 2]; v.w *= r * gk[lane * 4 + 3];
        split_store4(v, qh + qo + DIM_, ql + qo + DIM_);
    }
}

// ---------------- K5b: v -> vT per head, split ------------------------------
__global__ void k_vsplit(const float* __restrict__ qkv,
                         __nv_bfloat16* __restrict__ vh,
                         __nv_bfloat16* __restrict__ vl) {
    __shared__ float t[32][33];
    int z = blockIdx.z, b = z >> 4, h = z & 15;
    int s0 = blockIdx.x * 32, d0 = blockIdx.y * 32;
    const float* src = qkv + (long long)b * N_ * QKVC_ + 2 * DIM_ + h * DH_;
    for (int i = threadIdx.y; i < 32; i += 8)
        t[i][threadIdx.x] = src[(long long)(s0 + i) * QKVC_ + d0 + threadIdx.x];
    __syncthreads();
    long long ob = (long long)z * DH_ * N_;
    for (int i = threadIdx.y; i < 32; i += 8) {
        float v = t[threadIdx.x][i];
        long long o = ob + (long long)(d0 + i) * N_ + s0 + threadIdx.x;
        __nv_bfloat16 hh = __float2bfloat16(v);
        vh[o] = hh;
        vl[o] = __float2bfloat16(v - __bfloat162float(hh));
    }
}

// ---------------- K7: softmax rows -> attn hi/lo bf16 -----------------------
__global__ void k_softmax_split(const float* __restrict__ logits,
                                __nv_bfloat16* __restrict__ ah,
                                __nv_bfloat16* __restrict__ al) {
    long long row = blockIdx.x;
    const float4* p = (const float4*)(logits + row * (long long)N_);
    float4 v0 = p[threadIdx.x];
    float4 v1 = p[threadIdx.x + 256];
    float mx = fmaxf(fmaxf(fmaxf(v0.x, v0.y), fmaxf(v0.z, v0.w)),
                     fmaxf(fmaxf(v1.x, v1.y), fmaxf(v1.z, v1.w)));
    mx = blk_max256(mx);
    v0.x = __expf(v0.x - mx); v0.y = __expf(v0.y - mx);
    v0.z = __expf(v0.z - mx); v0.w = __expf(v0.w - mx);
    v1.x = __expf(v1.x - mx); v1.y = __expf(v1.y - mx);
    v1.z = __expf(v1.z - mx); v1.w = __expf(v1.w - mx);
    float s = v0.x + v0.y + v0.z + v0.w + v1.x + v1.y + v1.z + v1.w;
    s = blk_sum256(s);
    float inv = 1.f / s;
    v0.x *= inv; v0.y *= inv; v0.z *= inv; v0.w *= inv;
    v1.x *= inv; v1.y *= inv; v1.z *= inv; v1.w *= inv;
    long long base = row * (long long)N_;
    split_store4(v0, ah + base + threadIdx.x * 4, al + base + threadIdx.x * 4);
    split_store4(v1, ah + base + (threadIdx.x + 256) * 4,
                     al + base + (threadIdx.x + 256) * 4);
}

// ---------------------------------------------------------------------------
// mma.sync bf16x3 GEMM:  C = alpha * (Ahi+Alo)(Bhi+Blo)^T  (+ Cadd)
//   Block 128x128, 8 warps (warp tile 64x32), K-chunk 32, 3-stage cp.async,
//   XOR-swizzled 64B rows (chunk' = chunk ^ ((row>>1)&3): aligned + conflict-
//   free), term-sequenced fragments (low regs), 2 CTAs/SM.
// ---------------------------------------------------------------------------
#define CHUNK  32
#define ROWB   64
#define TILEB  (128 * ROWB)          // 8192 B
#define STAGEB (4 * TILEB)           // 32768 B
#define NSTAGE 3
#define GEMM_SMEM (NSTAGE * STAGEB)  // 98304 B

__global__ void __launch_bounds__(256, 2)
gemm_bf16x3(const __nv_bfloat16* __restrict__ Ahi, const __nv_bfloat16* __restrict__ Alo,
            int lda,
            const __nv_bfloat16* __restrict__ Bhi, const __nv_bfloat16* __restrict__ Blo,
            int ldb,
            const float* __restrict__ Cadd, float* __restrict__ C,
            __nv_bfloat16* __restrict__ Oh, __nv_bfloat16* __restrict__ Ol,
            int ldc, int K,
            long long sAb, long long sAh, long long sBb, long long sBh,
            long long sCb, long long sCh, int H, float alpha) {
    extern __shared__ char smem[];
    uint32_t sb = smem_u32(smem);
    int tid = threadIdx.x;
    int wid = tid >> 5, lane = tid & 31;
    int warp_m = wid >> 2;     // 0..1  -> 64 rows each
    int warp_n = wid & 3;      // 0..3  -> 32 cols each

    int z = blockIdx.z;
    int bb = z / H, hh = z - bb * H;
    long long aoff = bb * sAb + hh * sAh;
    long long boff = bb * sBb + hh * sBh;
    long long coff = bb * sCb + hh * sCh;
    Ahi += aoff; Alo += aoff;
    Bhi += boff; Blo += boff;
    C += coff;
    if (Cadd) Cadd += coff;
    if (Oh) { Oh += coff; Ol += coff; }

    int row0 = blockIdx.y * 128;
    int col0 = blockIdx.x * 128;

    float acc[4][4][4];
    #pragma unroll
    for (int i = 0; i < 4; i++)
        #pragma unroll
        for (int j = 0; j < 4; j++)
            #pragma unroll
            for (int r = 0; r < 4; r++) acc[i][j][r] = 0.f;

    int NC = K / CHUNK;

    // store: row rid, 16B chunk seg -> offset rid*64 + (seg ^ ((rid>>1)&3))*16
    auto load_stage = [&](int slot, int k0) {
        uint32_t base = sb + slot * STAGEB;
        #pragma unroll
        for (int t = 0; t < 4; t++) {
            const __nv_bfloat16* p = (t == 0) ? Ahi : (t == 1) ? Alo
                                   : (t == 2) ? Bhi : Blo;
            int r0g = (t < 2) ? row0 : col0;
            int ld  = (t < 2) ? lda : ldb;
            #pragma unroll
            for (int j = 0; j < 2; j++) {
                int id  = tid + j * 256;      // 0..511
                int rid = id >> 2;            // row 0..127
                int seg = id & 3;             // logical 16B chunk
                int sw  = seg ^ ((rid >> 1) & 3);
                cp16(base + (uint32_t)t * TILEB + (uint32_t)(rid * ROWB + sw * 16),
                     p + (long long)(r0g + rid) * ld + k0 + seg * 8);
            }
        }
        cp_commit();
    };

    load_stage(0, 0);
    load_stage(1, CHUNK);

    int lr  = lane & 15;                // ldmatrix row within 16
    int cx  = lane >> 4;                // logical chunk half (0/1)
    int swz = (lr >> 1) & 3;            // per-thread swizzle key

    for (int i = 0; i < NC; i++) {
        if (i < NC - 1) cp_wait<1>();
        else            cp_wait<0>();
        __syncthreads();
        if (i + 2 < NC) load_stage((i + 2) % NSTAGE, (i + 2) * CHUNK);

        int slot = i % NSTAGE;
        uint32_t abase = sb + slot * STAGEB + (uint32_t)((warp_m * 64 + lr) * ROWB);
        uint32_t bbase = sb + slot * STAGEB + 2 * TILEB
                       + (uint32_t)((warp_n * 32 + lr) * ROWB);

        #pragma unroll
        for (int s = 0; s < 2; s++) {
            uint32_t co = (uint32_t)(((s << 1) | cx) ^ swz) << 4;  // swizzled col
            uint32_t A1[4][4], A2[4][4], Bf[4][2];
            // Ah + Bh
            #pragma unroll
            for (int mi = 0; mi < 4; mi++)
                ldsm4(A1[mi][0], A1[mi][1], A1[mi][2], A1[mi][3],
                      abase + (uint32_t)(mi * 16 * ROWB) + co);
            #pragma unroll
            for (int np = 0; np < 2; np++) {
                uint32_t r0, r1, r2, r3;
                ldsm4(r0, r1, r2, r3, bbase + (uint32_t)(np * 16 * ROWB) + co);
                Bf[2 * np][0] = r0; Bf[2 * np][1] = r2;
                Bf[2 * np + 1][0] = r1; Bf[2 * np + 1][1] = r3;
            }
            // hi*hi
            #pragma unroll
            for (int mi = 0; mi < 4; mi++)
                #pragma unroll
                for (int ni = 0; ni < 4; ni++)
                    mma16816(acc[mi][ni], A1[mi], Bf[ni]);
            // Al, then lo*hi (A2 x Bh still in Bf)
            #pragma unroll
            for (int mi = 0; mi < 4; mi++)
                ldsm4(A2[mi][0], A2[mi][1], A2[mi][2], A2[mi][3],
                      abase + (uint32_t)(mi * 16 * ROWB) + co + TILEB);
            #pragma unroll
            for (int mi = 0; mi < 4; mi++)
                #pragma unroll
                for (int ni = 0; ni < 4; ni++)
                    mma16816(acc[mi][ni], A2[mi], Bf[ni]);
            // Bl overwrites Bf, then hi*lo (A1 x Bl)
            #pragma unroll
            for (int np = 0; np < 2; np++) {
                uint32_t r0, r1, r2, r3;
                ldsm4(r0, r1, r2, r3,
                      bbase + (uint32_t)(np * 16 * ROWB) + co + TILEB);
                Bf[2 * np][0] = r0; Bf[2 * np][1] = r2;
                Bf[2 * np + 1][0] = r1; Bf[2 * np + 1][1] = r3;
            }
            #pragma unroll
            for (int mi = 0; mi < 4; mi++)
                #pragma unroll
                for (int ni = 0; ni < 4; ni++)
                    mma16816(acc[mi][ni], A1[mi], Bf[ni]);
        }
    }

    // ---- epilogue ------------------------------------------------------
    bool addc = (Cadd != nullptr);
    bool split = (Oh != nullptr);
    int mrow = row0 + warp_m * 64 + (lane >> 2);
    int ccol = col0 + warp_n * 32 + (lane & 3) * 2;
    #pragma unroll
    for (int mi = 0; mi < 4; mi++) {
        #pragma unroll
        for (int ni = 0; ni < 4; ni++) {
            long long o0 = (long long)(mrow + mi * 16) * ldc + ccol + ni * 8;
            long long o1 = o0 + 8LL * ldc;
            float2 v0 = make_float2(acc[mi][ni][0] * alpha, acc[mi][ni][1] * alpha);
            float2 v1 = make_float2(acc[mi][ni][2] * alpha, acc[mi][ni][3] * alpha);
            if (addc) {
                float2 c0 = *(const float2*)(Cadd + o0);
                float2 c1 = *(const float2*)(Cadd + o1);
                v0.x += c0.x; v0.y += c0.y;
                v1.x += c1.x; v1.y += c1.y;
            }
            *(float2*)(C + o0) = v0;
            *(float2*)(C + o1) = v1;
            if (split) {
                *(uint32_t*)(Oh + o0) = pack_hi2(v0.x, v0.y);
                *(uint32_t*)(Ol + o0) = pack_lo2(v0.x, v0.y);
                *(uint32_t*)(Oh + o1) = pack_hi2(v1.x, v1.y);
                *(uint32_t*)(Ol + o1) = pack_lo2(v1.x, v1.y);
            }
        }
    }
}

// ---------------------------------------------------------------------------
extern "C" void kernel_launch(void* const* d_in, const int* in_sizes, int n_in,
                              void* d_out, int out_size) {
    const float* x      = (const float*)d_in[0];
    const float* emb    = (const float*)d_in[1];
    const float* W_emb  = (const float*)d_in[2];
    const float* b_emb  = (const float*)d_in[3];
    const float* g_norm = (const float*)d_in[4];
    const float* W_qkv  = (const float*)d_in[5];
    const float* g_q    = (const float*)d_in[6];
    const float* g_k    = (const float*)d_in[7];
    const float* W_out  = (const float*)d_in[8];
    float* out = (float*)d_out;
    (void)in_sizes; (void)n_in; (void)out_size;

    float *ss, *qkv, *logits, *otok;
    __nv_bfloat16 *xnh, *xnl, *wqTh, *wqTl, *woTh, *woTl;
    __nv_bfloat16 *qkh, *qkl, *vTh, *vTl, *ah, *al, *oh, *ol;
    cudaGetSymbolAddress((void**)&ss,     g_ss);
    cudaGetSymbolAddress((void**)&xnh,    g_xnh);
    cudaGetSymbolAddress((void**)&xnl,    g_xnl);
    cudaGetSymbolAddress((void**)&wqTh,   g_wqTh);
    cudaGetSymbolAddress((void**)&wqTl,   g_wqTl);
    cudaGetSymbolAddress((void**)&woTh,   g_woTh);
    cudaGetSymbolAddress((void**)&woTl,   g_woTl);
    cudaGetSymbolAddress((void**)&qkv,    g_qkv);
    cudaGetSymbolAddress((void**)&qkh,    g_qkh);
    cudaGetSymbolAddress((void**)&qkl,    g_qkl);
    cudaGetSymbolAddress((void**)&vTh,    g_vTh);
    cudaGetSymbolAddress((void**)&vTl,    g_vTl);
    cudaGetSymbolAddress((void**)&logits, g_logits);
    cudaGetSymbolAddress((void**)&ah,     g_ah);
    cudaGetSymbolAddress((void**)&al,     g_al);
    cudaGetSymbolAddress((void**)&otok,   g_otok);
    cudaGetSymbolAddress((void**)&oh,     g_oh);
    cudaGetSymbolAddress((void**)&ol,     g_ol);

    cudaFuncSetAttribute(gemm_bf16x3,
                         cudaFuncAttributeMaxDynamicSharedMemorySize, GEMM_SMEM);

    const float att_scale = 0.08838834764831845f;   // 1/sqrt(128)

    // 1) scale/shift
    k_scale_shift<<<dim3((2 * DIM_) / 256, B_), 256>>>(emb, W_emb, b_emb, ss);

    // 2) AdaLN RMSNorm -> xn hi/lo
    k_xnorm<<<TOK_, 256>>>(x, g_norm, ss, xnh, xnl);

    // 3) transpose + split W_qkv
    k_tsplit<<<dim3(QKVC_ / 32, DIM_ / 32), dim3(32, 8)>>>(W_qkv, DIM_, QKVC_, wqTh, wqTl);

    // 4) QKV GEMM: [8192,2048] x [2048,6144] -> qkv fp32   (4th launch: profiled)
    gemm_bf16x3<<<dim3(QKVC_ / 128, TOK_ / 128, 1), 256, GEMM_SMEM>>>(
        xnh, xnl, DIM_, wqTh, wqTl, DIM_, nullptr, qkv, nullptr, nullptr, QKVC_,
        DIM_, 0, 0, 0, 0, 0, 0, 1, 1.0f);

    // 5) per-head q/k RMSNorm + split; v transpose + split
    k_qknorm_split<<<TOK_, 512>>>(qkv, g_q, g_k, qkh, qkl);
    k_vsplit<<<dim3(N_ / 32, DH_ / 32, BH_), dim3(32, 8)>>>(qkv, vTh, vTl);

    // 6) logits = q @ k^T * scale  (batched bh)
    gemm_bf16x3<<<dim3(N_ / 128, N_ / 128, BH_), 256, GEMM_SMEM>>>(
        qkh, qkl, 2 * DIM_, qkh + DIM_, qkl + DIM_, 2 * DIM_,
        nullptr, logits, nullptr, nullptr, N_,
        DH_,
        (long long)N_ * 2 * DIM_, DH_,
        (long long)N_ * 2 * DIM_, DH_,
        (long long)H_ * N_ * N_, (long long)N_ * N_,
        H_, att_scale);

    // 7) softmax -> attn hi/lo
    k_softmax_split<<<BH_ * N_, 256>>>(logits, ah, al);

    // 8) o = attn @ v  -> otok fp32 + fused hi/lo split
    gemm_bf16x3<<<dim3(1, N_ / 128, BH_), 256, GEMM_SMEM>>>(
        ah, al, N_, vTh, vTl, N_, nullptr, otok, oh, ol, DIM_,
        N_,
        (long long)H_ * N_ * N_, (long long)N_ * N_,
        (long long)H_ * DH_ * N_, (long long)DH_ * N_,
        (long long)N_ * DIM_, (long long)DH_,
        H_, 1.0f);

    // 9) transpose + split W_out
    k_tsplit<<<dim3(DIM_ / 32, DIM_ / 32), dim3(32, 8)>>>(W_out, DIM_, DIM_, woTh, woTl);

    // 10) out = o + o @ W_out
    gemm_bf16x3<<<dim3(DIM_ / 128, TOK_ / 128, 1), 256, GEMM_SMEM>>>(
        oh, ol, DIM_, woTh, woTl, DIM_, otok, out, nullptr, nullptr, DIM_,
        DIM_, 0, 0, 0, 0, 0, 0, 1, 1.0f);
}

// round 9
// speedup vs baseline: 2.2595x; 1.0703x over previous
#include <cuda_runtime.h>
#include <cuda_bf16.h>
#include <cstdint>

#define B_     4
#define N_     2048
#define DIM_   2048
#define H_     16
#define DH_    128
#define TOK_   (B_ * N_)
#define QKVC_  (3 * DIM_)
#define BH_    (B_ * H_)

__device__ float          g_ss[B_ * 2 * DIM_];
__device__ __nv_bfloat16  g_xnh[(long long)TOK_ * DIM_];
__device__ __nv_bfloat16  g_xnl[(long long)TOK_ * DIM_];
__device__ __nv_bfloat16  g_wqTh[(long long)QKVC_ * DIM_];
__device__ __nv_bfloat16  g_wqTl[(long long)QKVC_ * DIM_];
__device__ __nv_bfloat16  g_woTh[(long long)DIM_ * DIM_];
__device__ __nv_bfloat16  g_woTl[(long long)DIM_ * DIM_];
__device__ float          g_qkv[(long long)TOK_ * QKVC_];
__device__ __nv_bfloat16  g_qkh[(long long)TOK_ * 2 * DIM_];
__device__ __nv_bfloat16  g_qkl[(long long)TOK_ * 2 * DIM_];
__device__ __nv_bfloat16  g_vTh[(long long)BH_ * DH_ * N_];
__device__ __nv_bfloat16  g_vTl[(long long)BH_ * DH_ * N_];
__device__ float          g_otok[(long long)TOK_ * DIM_];
__device__ __nv_bfloat16  g_oh[(long long)TOK_ * DIM_];
__device__ __nv_bfloat16  g_ol[(long long)TOK_ * DIM_];

__device__ __forceinline__ uint32_t smem_u32(const void* p) {
    uint32_t a;
    asm("{ .reg .u64 t; cvta.to.shared.u64 t, %1; cvt.u32.u64 %0, t; }"
        : "=r"(a) : "l"(p));
    return a;
}
__device__ __forceinline__ void cp16(uint32_t dst, const void* src) {
    asm volatile("cp.async.cg.shared.global [%0], [%1], 16;"
                 :: "r"(dst), "l"(__cvta_generic_to_global(src)));
}
__device__ __forceinline__ void cp_commit() {
    asm volatile("cp.async.commit_group;" ::: "memory");
}
template <int NN>
__device__ __forceinline__ void cp_wait() {
    asm volatile("cp.async.wait_group %0;" :: "n"(NN) : "memory");
}
__device__ __forceinline__ void ldsm4(uint32_t& r0, uint32_t& r1,
                                      uint32_t& r2, uint32_t& r3, uint32_t a) {
    asm volatile("ldmatrix.sync.aligned.m8n8.x4.shared.b16 {%0,%1,%2,%3}, [%4];"
                 : "=r"(r0), "=r"(r1), "=r"(r2), "=r"(r3) : "r"(a));
}
__device__ __forceinline__ void mma16816(float* d, const uint32_t* a,
                                         const uint32_t* b) {
    asm volatile(
        "mma.sync.aligned.m16n8k16.row.col.f32.bf16.bf16.f32 "
        "{%0,%1,%2,%3}, {%4,%5,%6,%7}, {%8,%9}, {%0,%1,%2,%3};"
        : "+f"(d[0]), "+f"(d[1]), "+f"(d[2]), "+f"(d[3])
        : "r"(a[0]), "r"(a[1]), "r"(a[2]), "r"(a[3]), "r"(b[0]), "r"(b[1]));
}
__device__ __forceinline__ void st32(uint32_t a, uint32_t v) {
    asm volatile("st.shared.b32 [%0], %1;" :: "r"(a), "r"(v) : "memory");
}
__device__ __forceinline__ void split_store4(float4 v,
                                             __nv_bfloat16* __restrict__ hi,
                                             __nv_bfloat16* __restrict__ lo) {
    __nv_bfloat16 h[4], l[4];
    float f[4] = {v.x, v.y, v.z, v.w};
    #pragma unroll
    for (int i = 0; i < 4; i++) {
        h[i] = __float2bfloat16(f[i]);
        l[i] = __float2bfloat16(f[i] - __bfloat162float(h[i]));
    }
    *(uint2*)hi = *(const uint2*)h;
    *(uint2*)lo = *(const uint2*)l;
}
__device__ __forceinline__ uint32_t pack_hi2(float a, float b) {
    __nv_bfloat16 h[2] = {__float2bfloat16(a), __float2bfloat16(b)};
    return *(const uint32_t*)h;
}
__device__ __forceinline__ uint32_t pack_lo2(float a, float b) {
    __nv_bfloat16 ha = __float2bfloat16(a), hb = __float2bfloat16(b);
    __nv_bfloat16 l[2] = {__float2bfloat16(a - __bfloat162float(ha)),
                          __float2bfloat16(b - __bfloat162float(hb))};
    return *(const uint32_t*)l;
}
__device__ __forceinline__ float blk_sum256(float v) {
    __shared__ float red[8];
    __shared__ float tot;
    #pragma unroll
    for (int o = 16; o > 0; o >>= 1) v += __shfl_xor_sync(0xffffffffu, v, o);
    if ((threadIdx.x & 31) == 0) red[threadIdx.x >> 5] = v;
    __syncthreads();
    if (threadIdx.x == 0) {
        float s = 0.f;
        #pragma unroll
        for (int i = 0; i < 8; i++) s += red[i];
        tot = s;
    }
    __syncthreads();
    return tot;
}

__global__ void k_scale_shift(const float* __restrict__ emb,
                              const float* __restrict__ W,
                              const float* __restrict__ bias,
                              float* __restrict__ ss) {
    int c = blockIdx.x * 256 + threadIdx.x;
    int b = blockIdx.y;
    const float* e = emb + b * DIM_;
    float acc = bias[c];
    const float* wp = W + c;
    #pragma unroll 8
    for (int k = 0; k < DIM_; k++)
        acc = fmaf(e[k], wp[(long long)k * (2 * DIM_)], acc);
    ss[b * (2 * DIM_) + c] = acc;
}

__global__ void k_xnorm(const float* __restrict__ x,
                        const float* __restrict__ g,
                        const float* __restrict__ ss,
                        __nv_bfloat16* __restrict__ xh,
                        __nv_bfloat16* __restrict__ xl) {
    long long row = blockIdx.x;
    int b = (int)(row >> 11);
    const float4* xr = (const float4*)(x + row * DIM_);
    float4 v0 = xr[threadIdx.x];
    float4 v1 = xr[threadIdx.x + 256];
    float s = v0.x * v0.x + v0.y * v0.y + v0.z * v0.z + v0.w * v0.w
            + v1.x * v1.x + v1.y * v1.y + v1.z * v1.z + v1.w * v1.w;
    s = blk_sum256(s);
    float r = rsqrtf(s * (1.f / DIM_) + 1e-6f);
    const float* sc = ss + b * (2 * DIM_);
    const float* sh = sc + DIM_;
    int c0 = threadIdx.x * 4, c1 = (threadIdx.x + 256) * 4;
    float4 o0, o1;
    o0.x = fmaf(v0.x * r * g[c0 + 0], 1.f + sc[c0 + 0], sh[c0 + 0]);
    o0.y = fmaf(v0.y * r * g[c0 + 1], 1.f + sc[c0 + 1], sh[c0 + 1]);
    o0.z = fmaf(v0.z * r * g[c0 + 2], 1.f + sc[c0 + 2], sh[c0 + 2]);
    o0.w = fmaf(v0.w * r * g[c0 + 3], 1.f + sc[c0 + 3], sh[c0 + 3]);
    o1.x = fmaf(v1.x * r * g[c1 + 0], 1.f + sc[c1 + 0], sh[c1 + 0]);
    o1.y = fmaf(v1.y * r * g[c1 + 1], 1.f + sc[c1 + 1], sh[c1 + 1]);
    o1.z = fmaf(v1.z * r * g[c1 + 2], 1.f + sc[c1 + 2], sh[c1 + 2]);
    o1.w = fmaf(v1.w * r * g[c1 + 3], 1.f + sc[c1 + 3], sh[c1 + 3]);
    long long base = row * DIM_;
    split_store4(o0, xh + base + c0, xl + base + c0);
    split_store4(o1, xh + base + c1, xl + base + c1);
}

__global__ void k_tsplit(const float* __restrict__ W, int KR, int NC,
                         __nv_bfloat16* __restrict__ Th,
                         __nv_bfloat16* __restrict__ Tl) {
    __shared__ float t[32][33];
    int c0 = blockIdx.x * 32, r0 = blockIdx.y * 32;
    for (int i = threadIdx.y; i < 32; i += 8)
        t[i][threadIdx.x] = W[(long long)(r0 + i) * NC + c0 + threadIdx.x];
    __syncthreads();
    for (int i = threadIdx.y; i < 32; i += 8) {
        float v = t[threadIdx.x][i];
        long long o = (long long)(c0 + i) * KR + r0 + threadIdx.x;
        __nv_bfloat16 h = __float2bfloat16(v);
        Th[o] = h;
        Tl[o] = __float2bfloat16(v - __bfloat162float(h));
    }
}

__global__ void k_qknorm_split(const float* __restrict__ qkv,
                               const float* __restrict__ gq,
                               const float* __restrict__ gk,
                               __nv_bfloat16* __restrict__ qh,
                               __nv_bfloat16* __restrict__ ql) {
    int row = blockIdx.x;
    int h = threadIdx.x >> 5, lane = threadIdx.x & 31;
    const float* q = qkv + (long long)row * QKVC_ + h * DH_;
    const float* k = q + DIM_;
    long long qo = (long long)row * (2 * DIM_) + h * DH_ + lane * 4;
    {
        float4 v = *(const float4*)(q + lane * 4);
        float s = v.x * v.x + v.y * v.y + v.z * v.z + v.w * v.w;
        #pragma unroll
        for (int o = 16; o > 0; o >>= 1) s += __shfl_xor_sync(0xffffffffu, s, o);
        float r = rsqrtf(s * (1.f / DH_) + 1e-6f);
        v.x *= r * gq[lane * 4 + 0]; v.y *= r * gq[lane * 4 + 1];
        v.z *= r * gq[lane * 4 + 2]; v.w *= r * gq[lane * 4 + 3];
        split_store4(v, qh + qo, ql + qo);
    }
    {
        float4 v = *(const float4*)(k + lane * 4);
        float s = v.x * v.x + v.y * v.y + v.z * v.z + v.w * v.w;
        #pragma unroll
        for (int o = 16; o > 0; o >>= 1) s += __shfl_xor_sync(0xffffffffu, s, o);
        float r = rsqrtf(s * (1.f / DH_) + 1e-6f);
        v.x *= r * gk[lane * 4 + 0]; v.y *= r * gk[lane * 4 + 1];
        v.z *= r * gk[lane * 4 + 2]; v.w *= r * gk[lane * 4 + 3];
        split_store4(v, qh + qo + DIM_, ql + qo + DIM_);
    }
}

__global__ void k_vsplit(const float* __restrict__ qkv,
                         __nv_bfloat16* __restrict__ vh,
                         __nv_bfloat16* __restrict__ vl) {
    __shared__ float t[32][33];
    int z = blockIdx.z, b = z >> 4, h = z & 15;
    int s0 = blockIdx.x * 32, d0 = blockIdx.y * 32;
    const float* src = qkv + (long long)b * N_ * QKVC_ + 2 * DIM_ + h * DH_;
    for (int i = threadIdx.y; i < 32; i += 8)
        t[i][threadIdx.x] = src[(long long)(s0 + i) * QKVC_ + d0 + threadIdx.x];
    __syncthreads();
    long long ob = (long long)z * DH_ * N_;
    for (int i = threadIdx.y; i < 32; i += 8) {
        float v = t[threadIdx.x][i];
        long long o = ob + (long long)(d0 + i) * N_ + s0 + threadIdx.x;
        __nv_bfloat16 hh = __float2bfloat16(v);
        vh[o] = hh;
        vl[o] = __float2bfloat16(v - __bfloat162float(hh));
    }
}

// ------------- generic GEMM (unchanged R6 engine) ---------------------------
#define CHUNK  32
#define ROWB   64
#define TILEB  (128 * ROWB)
#define STAGEB (4 * TILEB)
#define NSTAGE 3
#define GEMM_SMEM (NSTAGE * STAGEB)

__global__ void __launch_bounds__(256, 2)
gemm_bf16x3(const __nv_bfloat16* __restrict__ Ahi, const __nv_bfloat16* __restrict__ Alo,
            int lda,
            const __nv_bfloat16* __restrict__ Bhi, const __nv_bfloat16* __restrict__ Blo,
            int ldb,
            const float* __restrict__ Cadd, float* __restrict__ C,
            int ldc, int K, float alpha) {
    extern __shared__ char smem[];
    uint32_t sb = smem_u32(smem);
    int tid = threadIdx.x, wid = tid >> 5, lane = tid & 31;
    int warp_m = wid >> 2, warp_n = wid & 3;
    int row0 = blockIdx.y * 128, col0 = blockIdx.x * 128;

    float acc[4][4][4];
    #pragma unroll
    for (int i = 0; i < 4; i++)
        #pragma unroll
        for (int j = 0; j < 4; j++)
            #pragma unroll
            for (int r = 0; r < 4; r++) acc[i][j][r] = 0.f;

    int NC = K / CHUNK;
    auto load_stage = [&](int slot, int k0) {
        uint32_t base = sb + slot * STAGEB;
        #pragma unroll
        for (int t = 0; t < 4; t++) {
            const __nv_bfloat16* p = (t == 0) ? Ahi : (t == 1) ? Alo
                                   : (t == 2) ? Bhi : Blo;
            int r0g = (t < 2) ? row0 : col0;
            int ld  = (t < 2) ? lda : ldb;
            #pragma unroll
            for (int j = 0; j < 2; j++) {
                int id = tid + j * 256, rid = id >> 2, seg = id & 3;
                int sw = seg ^ ((rid >> 1) & 3);
                cp16(base + (uint32_t)t * TILEB + (uint32_t)(rid * ROWB + sw * 16),
                     p + (long long)(r0g + rid) * ld + k0 + seg * 8);
            }
        }
        cp_commit();
    };
    load_stage(0, 0);
    load_stage(1, CHUNK);

    int lr = lane & 15, cx = lane >> 4, swz = (lr >> 1) & 3;
    for (int i = 0; i < NC; i++) {
        if (i < NC - 1) cp_wait<1>(); else cp_wait<0>();
        __syncthreads();
        if (i + 2 < NC) load_stage((i + 2) % NSTAGE, (i + 2) * CHUNK);
        int slot = i % NSTAGE;
        uint32_t abase = sb + slot * STAGEB + (uint32_t)((warp_m * 64 + lr) * ROWB);
        uint32_t bbase = sb + slot * STAGEB + 2 * TILEB
                       + (uint32_t)((warp_n * 32 + lr) * ROWB);
        #pragma unroll
        for (int s = 0; s < 2; s++) {
            uint32_t co = (uint32_t)(((s << 1) | cx) ^ swz) << 4;
            uint32_t A1[4][4], A2[4][4], Bf[4][2];
            #pragma unroll
            for (int mi = 0; mi < 4; mi++)
                ldsm4(A1[mi][0], A1[mi][1], A1[mi][2], A1[mi][3],
                      abase + (uint32_t)(mi * 16 * ROWB) + co);
            #pragma unroll
            for (int np = 0; np < 2; np++) {
                uint32_t r0, r1, r2, r3;
                ldsm4(r0, r1, r2, r3, bbase + (uint32_t)(np * 16 * ROWB) + co);
                Bf[2 * np][0] = r0; Bf[2 * np][1] = r2;
                Bf[2 * np + 1][0] = r1; Bf[2 * np + 1][1] = r3;
            }
            #pragma unroll
            for (int mi = 0; mi < 4; mi++)
                #pragma unroll
                for (int ni = 0; ni < 4; ni++)
                    mma16816(acc[mi][ni], A1[mi], Bf[ni]);
            #pragma unroll
            for (int mi = 0; mi < 4; mi++)
                ldsm4(A2[mi][0], A2[mi][1], A2[mi][2], A2[mi][3],
                      abase + (uint32_t)(mi * 16 * ROWB) + co + TILEB);
            #pragma unroll
            for (int mi = 0; mi < 4; mi++)
                #pragma unroll
                for (int ni = 0; ni < 4; ni++)
                    mma16816(acc[mi][ni], A2[mi], Bf[ni]);
            #pragma unroll
            for (int np = 0; np < 2; np++) {
                uint32_t r0, r1, r2, r3;
                ldsm4(r0, r1, r2, r3,
                      bbase + (uint32_t)(np * 16 * ROWB) + co + TILEB);
                Bf[2 * np][0] = r0; Bf[2 * np][1] = r2;
                Bf[2 * np + 1][0] = r1; Bf[2 * np + 1][1] = r3;
            }
            #pragma unroll
            for (int mi = 0; mi < 4; mi++)
                #pragma unroll
                for (int ni = 0; ni < 4; ni++)
                    mma16816(acc[mi][ni], A1[mi], Bf[ni]);
        }
    }
    bool addc = (Cadd != nullptr);
    int mrow = row0 + warp_m * 64 + (lane >> 2);
    int ccol = col0 + warp_n * 32 + (lane & 3) * 2;
    #pragma unroll
    for (int mi = 0; mi < 4; mi++)
        #pragma unroll
        for (int ni = 0; ni < 4; ni++) {
            long long o0 = (long long)(mrow + mi * 16) * ldc + ccol + ni * 8;
            long long o1 = o0 + 8LL * ldc;
            float2 v0 = make_float2(acc[mi][ni][0] * alpha, acc[mi][ni][1] * alpha);
            float2 v1 = make_float2(acc[mi][ni][2] * alpha, acc[mi][ni][3] * alpha);
            if (addc) {
                float2 c0 = *(const float2*)(Cadd + o0);
                float2 c1 = *(const float2*)(Cadd + o1);
                v0.x += c0.x; v0.y += c0.y; v1.x += c1.x; v1.y += c1.y;
            }
            *(float2*)(C + o0) = v0;
            *(float2*)(C + o1) = v1;
        }
}

// ------------- flash attention ----------------------------------------------
#define FSTG   24576
#define F_BH   8192
#define FVSTG  16384
#define F_P    73728
#define F_RM   106496
#define F_RS   107520
#define F_M    108544
#define F_L    108800
#define FLASH_SMEM 109056

__global__ void __launch_bounds__(256, 2)
flash_attn(const __nv_bfloat16* __restrict__ qkh, const __nv_bfloat16* __restrict__ qkl,
           const __nv_bfloat16* __restrict__ vTh, const __nv_bfloat16* __restrict__ vTl,
           float* __restrict__ otok, __nv_bfloat16* __restrict__ oh,
           __nv_bfloat16* __restrict__ ol) {
    extern __shared__ char smem[];
    uint32_t sb = smem_u32(smem);
    int tid = threadIdx.x, lane = tid & 31, wid = tid >> 5;
    int fm = wid >> 2, fn = wid & 3;
    int lr = lane & 15, cx = lane >> 4, swz = (lr >> 1) & 3;
    int qt = blockIdx.x, z = blockIdx.y, b = z >> 4, h = z & 15;
    long long qrow0 = (long long)b * N_ + qt * 64;
    long long krow0 = (long long)b * N_;
    int hcol = h * DH_;
    long long zoff = (long long)z * DH_ * N_;
    const float SCALE = 0.08838834764831845f;

    float* RM = (float*)(smem + F_RM);
    float* RS = (float*)(smem + F_RS);
    float* Mv = (float*)(smem + F_M);
    float* Lv = (float*)(smem + F_L);
    if (tid < 64) { Mv[tid] = -1e30f; Lv[tid] = 0.f; }

    float oacc[2][4][4];
    #pragma unroll
    for (int mi = 0; mi < 2; mi++)
        #pragma unroll
        for (int ni = 0; ni < 4; ni++)
            #pragma unroll
            for (int e = 0; e < 4; e++) oacc[mi][ni][e] = 0.f;

    auto load_s = [&](int slot, int c, int j) {
        uint32_t base = sb + slot * FSTG;
        {
            int rid = tid >> 2, seg = tid & 3;
            int sw = seg ^ ((rid >> 1) & 3);
            long long off = (qrow0 + rid) * (2LL * DIM_) + hcol + c * 32 + seg * 8;
            uint32_t d = base + (uint32_t)(rid * 64 + sw * 16);
            cp16(d, qkh + off);
            cp16(d + 4096, qkl + off);
        }
        #pragma unroll
        for (int t = 0; t < 2; t++) {
            int id = tid + t * 256, rid = id >> 2, seg = id & 3;
            int sw = seg ^ ((rid >> 1) & 3);
            long long off = (krow0 + j * 128 + rid) * (2LL * DIM_)
                          + hcol + DIM_ + c * 32 + seg * 8;
            uint32_t d = base + F_BH + (uint32_t)(rid * 64 + sw * 16);
            cp16(d, qkh + off);
            cp16(d + 8192, qkl + off);
        }
        cp_commit();
    };
    auto load_v = [&](int slot, int c, int j) {
        uint32_t base = sb + slot * FVSTG;
        #pragma unroll
        for (int t = 0; t < 2; t++) {
            int id = tid + t * 256, rid = id >> 2, seg = id & 3;
            int sw = seg ^ ((rid >> 1) & 3);
            long long off = zoff + (long long)rid * N_ + j * 128 + c * 32 + seg * 8;
            uint32_t d = base + (uint32_t)(rid * 64 + sw * 16);
            cp16(d, vTh + off);
            cp16(d + 8192, vTl + off);
        }
        cp_commit();
    };

    int rbase = fm * 32 + (lane >> 2);
    int cq = (lane & 3) * 2;

    for (int j = 0; j < 16; j++) {
        float sacc[2][4][4];
        #pragma unroll
        for (int mi = 0; mi < 2; mi++)
            #pragma unroll
            for (int ni = 0; ni < 4; ni++)
                #pragma unroll
                for (int e = 0; e < 4; e++) sacc[mi][ni][e] = 0.f;

        load_s(0, 0, j);
        load_s(1, 1, j);
        for (int c = 0; c < 4; c++) {
            if (c < 3) cp_wait<1>(); else cp_wait<0>();
            __syncthreads();
            if (c + 2 < 4) load_s((c + 2) % 3, c + 2, j);
            uint32_t abase = sb + (c % 3) * FSTG + (uint32_t)((fm * 32 + lr) * 64);
            uint32_t bbase = sb + (c % 3) * FSTG + F_BH + (uint32_t)((fn * 32 + lr) * 64);
            #pragma unroll
            for (int s = 0; s < 2; s++) {
                uint32_t co = (uint32_t)(((s << 1) | cx) ^ swz) << 4;
                uint32_t A1[2][4], A2[2][4], Bf[4][2];
                #pragma unroll
                for (int mi = 0; mi < 2; mi++)
                    ldsm4(A1[mi][0], A1[mi][1], A1[mi][2], A1[mi][3],
                          abase + (uint32_t)(mi * 1024) + co);
                #pragma unroll
                for (int np = 0; np < 2; np++) {
                    uint32_t r0, r1, r2, r3;
                    ldsm4(r0, r1, r2, r3, bbase + (uint32_t)(np * 1024) + co);
                    Bf[2 * np][0] = r0; Bf[2 * np][1] = r2;
                    Bf[2 * np + 1][0] = r1; Bf[2 * np + 1][1] = r3;
                }
                #pragma unroll
                for (int mi = 0; mi < 2; mi++)
                    #pragma unroll
                    for (int ni = 0; ni < 4; ni++)
                        mma16816(sacc[mi][ni], A1[mi], Bf[ni]);
                #pragma unroll
                for (int mi = 0; mi < 2; mi++)
                    ldsm4(A2[mi][0], A2[mi][1], A2[mi][2], A2[mi][3],
                          abase + (uint32_t)(mi * 1024) + co + 4096);
                #pragma unroll
                for (int mi = 0; mi < 2; mi++)
                    #pragma unroll
                    for (int ni = 0; ni < 4; ni++)
                        mma16816(sacc[mi][ni], A2[mi], Bf[ni]);
                #pragma unroll
                for (int np = 0; np < 2; np++) {
                    uint32_t r0, r1, r2, r3;
                    ldsm4(r0, r1, r2, r3, bbase + (uint32_t)(np * 1024) + co + 8192);
                    Bf[2 * np][0] = r0; Bf[2 * np][1] = r2;
                    Bf[2 * np + 1][0] = r1; Bf[2 * np + 1][1] = r3;
                }
                #pragma unroll
                for (int mi = 0; mi < 2; mi++)
                    #pragma unroll
                    for (int ni = 0; ni < 4; ni++)
                        mma16816(sacc[mi][ni], A1[mi], Bf[ni]);
            }
        }

        // online softmax
        float rmax[2][2];
        #pragma unroll
        for (int mi = 0; mi < 2; mi++)
            #pragma unroll
            for (int h2 = 0; h2 < 2; h2++) {
                float m = -1e30f;
                #pragma unroll
                for (int ni = 0; ni < 4; ni++) {
                    sacc[mi][ni][h2 * 2]     *= SCALE;
                    sacc[mi][ni][h2 * 2 + 1] *= SCALE;
                    m = fmaxf(m, fmaxf(sacc[mi][ni][h2 * 2], sacc[mi][ni][h2 * 2 + 1]));
                }
                #pragma unroll
                for (int o = 1; o <= 2; o <<= 1)
                    m = fmaxf(m, __shfl_xor_sync(0xffffffffu, m, o));
                rmax[mi][h2] = m;
            }
        if ((lane & 3) == 0)
            #pragma unroll
            for (int mi = 0; mi < 2; mi++)
                #pragma unroll
                for (int h2 = 0; h2 < 2; h2++)
                    RM[(rbase + mi * 16 + h2 * 8) * 4 + fn] = rmax[mi][h2];
        __syncthreads();

        float mnew[2][2], fact[2][2], rsum[2][2];
        #pragma unroll
        for (int mi = 0; mi < 2; mi++)
            #pragma unroll
            for (int h2 = 0; h2 < 2; h2++) {
                int r = rbase + mi * 16 + h2 * 8;
                float bm = fmaxf(fmaxf(RM[r * 4 + 0], RM[r * 4 + 1]),
                                 fmaxf(RM[r * 4 + 2], RM[r * 4 + 3]));
                float mo = Mv[r];
                float mn = fmaxf(mo, bm);
                mnew[mi][h2] = mn;
                fact[mi][h2] = __expf(mo - mn);
                rsum[mi][h2] = 0.f;
            }
        #pragma unroll
        for (int mi = 0; mi < 2; mi++)
            #pragma unroll
            for (int ni = 0; ni < 4; ni++)
                #pragma unroll
                for (int e = 0; e < 4; e++) {
                    int h2 = e >> 1;
                    oacc[mi][ni][e] *= fact[mi][h2];
                    float p = __expf(sacc[mi][ni][e] - mnew[mi][h2]);
                    sacc[mi][ni][e] = p;
                    rsum[mi][h2] += p;
                }
        #pragma unroll
        for (int o = 1; o <= 2; o <<= 1)
            #pragma unroll
            for (int mi = 0; mi < 2; mi++)
                #pragma unroll
                for (int h2 = 0; h2 < 2; h2++)
                    rsum[mi][h2] += __shfl_xor_sync(0xffffffffu, rsum[mi][h2], o);
        if ((lane & 3) == 0)
            #pragma unroll
            for (int mi = 0; mi < 2; mi++)
                #pragma unroll
                for (int h2 = 0; h2 < 2; h2++)
                    RS[(rbase + mi * 16 + h2 * 8) * 4 + fn] = rsum[mi][h2];
        // P -> smem (A-tile format, chunk index = fn)
        #pragma unroll
        for (int mi = 0; mi < 2; mi++)
            #pragma unroll
            for (int h2 = 0; h2 < 2; h2++) {
                int rl = rbase + mi * 16 + h2 * 8;
                int key = (rl >> 1) & 3;
                uint32_t rowb = sb + F_P + (uint32_t)(fn * 4096) + (uint32_t)(rl * 64);
                #pragma unroll
                for (int ni = 0; ni < 4; ni++) {
                    int cc = cq + ni * 8;
                    uint32_t boff = rowb
                        + (uint32_t)((((cc >> 3) ^ key) << 4) + (cc & 7) * 2);
                    float p0 = sacc[mi][ni][h2 * 2];
                    float p1 = sacc[mi][ni][h2 * 2 + 1];
                    st32(boff,         pack_hi2(p0, p1));
                    st32(boff + 16384, pack_lo2(p0, p1));
                }
            }
        __syncthreads();
        if (fn == 0 && (lane & 3) == 0)
            #pragma unroll
            for (int mi = 0; mi < 2; mi++)
                #pragma unroll
                for (int h2 = 0; h2 < 2; h2++) {
                    int r = rbase + mi * 16 + h2 * 8;
                    Mv[r] = mnew[mi][h2];
                    Lv[r] = Lv[r] * fact[mi][h2]
                          + RS[r * 4] + RS[r * 4 + 1] + RS[r * 4 + 2] + RS[r * 4 + 3];
                }

        // O += P @ V^T
        load_v(0, 0, j);
        load_v(1, 1, j);
        for (int c = 0; c < 4; c++) {
            if (c < 3) cp_wait<1>(); else cp_wait<0>();
            __syncthreads();
            if (c + 2 < 4) load_v((c + 2) % 3, c + 2, j);
            uint32_t pbase = sb + F_P + (uint32_t)(c * 4096)
                           + (uint32_t)((fm * 32 + lr) * 64);
            uint32_t vbase = sb + (c % 3) * FVSTG + (uint32_t)((fn * 32 + lr) * 64);
            #pragma unroll
            for (int s = 0; s < 2; s++) {
                uint32_t co = (uint32_t)(((s << 1) | cx) ^ swz) << 4;
                uint32_t A1[2][4], A2[2][4], Bf[4][2];
                #pragma unroll
                for (int mi = 0; mi < 2; mi++)
                    ldsm4(A1[mi][0], A1[mi][1], A1[mi][2], A1[mi][3],
                          pbase + (uint32_t)(mi * 1024) + co);
                #pragma unroll
                for (int np = 0; np < 2; np++) {
                    uint32_t r0, r1, r2, r3;
                    ldsm4(r0, r1, r2, r3, vbase + (uint32_t)(np * 1024) + co);
                    Bf[2 * np][0] = r0; Bf[2 * np][1] = r2;
                    Bf[2 * np + 1][0] = r1; Bf[2 * np + 1][1] = r3;
                }
                #pragma unroll
                for (int mi = 0; mi < 2; mi++)
                    #pragma unroll
                    for (int ni = 0; ni < 4; ni++)
                        mma16816(oacc[mi][ni], A1[mi], Bf[ni]);
                #pragma unroll
                for (int mi = 0; mi < 2; mi++)
                    ldsm4(A2[mi][0], A2[mi][1], A2[mi][2], A2[mi][3],
                          pbase + (uint32_t)(mi * 1024) + co + 16384);
                #pragma unroll
                for (int mi = 0; mi < 2; mi++)
                    #pragma unroll
                    for (int ni = 0; ni < 4; ni++)
                        mma16816(oacc[mi][ni], A2[mi], Bf[ni]);
                #pragma unroll
                for (int np = 0; np < 2; np++) {
                    uint32_t r0, r1, r2, r3;
                    ldsm4(r0, r1, r2, r3, vbase + (uint32_t)(np * 1024) + co + 8192);
                    Bf[2 * np][0] = r0; Bf[2 * np][1] = r2;
                    Bf[2 * np + 1][0] = r1; Bf[2 * np + 1][1] = r3;
                }
                #pragma unroll
                for (int mi = 0; mi < 2; mi++)
                    #pragma unroll
                    for (int ni = 0; ni < 4; ni++)
                        mma16816(oacc[mi][ni], A1[mi], Bf[ni]);
            }
        }
        __syncthreads();
    }

    #pragma unroll
    for (int mi = 0; mi < 2; mi++)
        #pragma unroll
        for (int h2 = 0; h2 < 2; h2++) {
            int rl = rbase + mi * 16 + h2 * 8;
            float li = 1.f / Lv[rl];
            long long row = (qrow0 + rl) * (long long)DIM_ + hcol + fn * 32;
            #pragma unroll
            for (int ni = 0; ni < 4; ni++) {
                float v0 = oacc[mi][ni][h2 * 2] * li;
                float v1 = oacc[mi][ni][h2 * 2 + 1] * li;
                long long o = row + cq + ni * 8;
                *(float2*)(otok + o) = make_float2(v0, v1);
                *(uint32_t*)(oh + o) = pack_hi2(v0, v1);
                *(uint32_t*)(ol + o) = pack_lo2(v0, v1);
            }
        }
}

// ---------------------------------------------------------------------------
extern "C" void kernel_launch(void* const* d_in, const int* in_sizes, int n_in,
                              void* d_out, int out_size) {
    const float* x      = (const float*)d_in[0];
    const float* emb    = (const float*)d_in[1];
    const float* W_emb  = (const float*)d_in[2];
    const float* b_emb  = (const float*)d_in[3];
    const float* g_norm = (const float*)d_in[4];
    const float* W_qkv  = (const float*)d_in[5];
    const float* g_q    = (const float*)d_in[6];
    const float* g_k    = (const float*)d_in[7];
    const float* W_out  = (const float*)d_in[8];
    float* out = (float*)d_out;
    (void)in_sizes; (void)n_in; (void)out_size;

    float *ss, *qkv, *otok;
    __nv_bfloat16 *xnh, *xnl, *wqTh, *wqTl, *woTh, *woTl;
    __nv_bfloat16 *qkh, *qkl, *vTh, *vTl, *oh, *ol;
    cudaGetSymbolAddress((void**)&ss,   g_ss);
    cudaGetSymbolAddress((void**)&xnh,  g_xnh);
    cudaGetSymbolAddress((void**)&xnl,  g_xnl);
    cudaGetSymbolAddress((void**)&wqTh, g_wqTh);
    cudaGetSymbolAddress((void**)&wqTl, g_wqTl);
    cudaGetSymbolAddress((void**)&woTh, g_woTh);
    cudaGetSymbolAddress((void**)&woTl, g_woTl);
    cudaGetSymbolAddress((void**)&qkv,  g_qkv);
    cudaGetSymbolAddress((void**)&qkh,  g_qkh);
    cudaGetSymbolAddress((void**)&qkl,  g_qkl);
    cudaGetSymbolAddress((void**)&vTh,  g_vTh);
    cudaGetSymbolAddress((void**)&vTl,  g_vTl);
    cudaGetSymbolAddress((void**)&otok, g_otok);
    cudaGetSymbolAddress((void**)&oh,   g_oh);
    cudaGetSymbolAddress((void**)&ol,   g_ol);

    cudaFuncSetAttribute(gemm_bf16x3,
                         cudaFuncAttributeMaxDynamicSharedMemorySize, GEMM_SMEM);
    cudaFuncSetAttribute(flash_attn,
                         cudaFuncAttributeMaxDynamicSharedMemorySize, FLASH_SMEM);

    k_scale_shift<<<dim3((2 * DIM_) / 256, B_), 256>>>(emb, W_emb, b_emb, ss);
    k_xnorm<<<TOK_, 256>>>(x, g_norm, ss, xnh, xnl);
    k_tsplit<<<dim3(QKVC_ / 32, DIM_ / 32), dim3(32, 8)>>>(W_qkv, DIM_, QKVC_, wqTh, wqTl);
    gemm_bf16x3<<<dim3(QKVC_ / 128, TOK_ / 128, 1), 256, GEMM_SMEM>>>(
        xnh, xnl, DIM_, wqTh, wqTl, DIM_, nullptr, qkv, QKVC_, DIM_, 1.0f);
    k_qknorm_split<<<TOK_, 512>>>(qkv, g_q, g_k, qkh, qkl);
    k_vsplit<<<dim3(N_ / 32, DH_ / 32, BH_), dim3(32, 8)>>>(qkv, vTh, vTl);
    flash_attn<<<dim3(N_ / 64, BH_), 256, FLASH_SMEM>>>(
        qkh, qkl, vTh, vTl, otok, oh, ol);
    k_tsplit<<<dim3(DIM_ / 32, DIM_ / 32), dim3(32, 8)>>>(W_out, DIM_, DIM_, woTh, woTl);
    gemm_bf16x3<<<dim3(DIM_ / 128, TOK_ / 128, 1), 256, GEMM_SMEM>>>(
        oh, ol, DIM_, woTh, woTl, DIM_, otok, out, DIM_, DIM_, 1.0f);
}